// round 13
// baseline (speedup 1.0000x reference)
#include <cuda_runtime.h>
#include <cstdint>
#include <math.h>

#define HEADS 6
static constexpr size_t MAXELEM = (size_t)4096 * 64 * 192;

__device__ float g_q[MAXELEM];
__device__ float g_k[MAXELEM];
__device__ float g_v[MAXELEM];
__device__ float g_t[MAXELEM];
__device__ float g_bias[HEADS * 64 * 64];
__device__ float g_scale[HEADS];
__device__ float g_tab[225 * 6];

// ---------------- helpers ----------------
__device__ __forceinline__ uint32_t f2tf(float x) {
    uint32_t u;
    asm("cvt.rna.tf32.f32 %0, %1;" : "=r"(u) : "f"(x));
    return u;
}
__device__ __forceinline__ float tf32r(float x) { return __uint_as_float(f2tf(x)); }

__device__ __forceinline__ void mma8(float c[4], const uint32_t a[4], const uint32_t b[2]) {
    asm volatile(
        "mma.sync.aligned.m16n8k8.row.col.f32.tf32.tf32.f32 "
        "{%0,%1,%2,%3}, {%4,%5,%6,%7}, {%8,%9}, {%0,%1,%2,%3};"
        : "+f"(c[0]), "+f"(c[1]), "+f"(c[2]), "+f"(c[3])
        : "r"(a[0]), "r"(a[1]), "r"(a[2]), "r"(a[3]), "r"(b[0]), "r"(b[1]));
}

__device__ __forceinline__ uint32_t smem_u32(const void* p) {
    uint32_t a;
    asm("{ .reg .u64 t; cvta.to.shared.u64 t, %1; cvt.u32.u64 %0, t; }" : "=r"(a) : "l"(p));
    return a;
}
__device__ __forceinline__ void cp16(uint32_t dst, const void* src) {
    asm volatile("cp.async.cg.shared.global [%0], [%1], 16;" :: "r"(dst), "l"(src) : "memory");
}
__device__ __forceinline__ void cp_commit() {
    asm volatile("cp.async.commit_group;" ::: "memory");
}
template <int N>
__device__ __forceinline__ void cp_wait() {
    asm volatile("cp.async.wait_group %0;" :: "n"(N) : "memory");
}

// ---------------- bias / scale precompute (parallel) ----------------
__device__ __forceinline__ float slog(float d) {
    float x = d * (8.0f / 7.0f);
    float a = fabsf(x);
    float v = log2f(a + 1.0f) * (1.0f / 3.0f);
    return (x > 0.f) ? v : ((x < 0.f) ? -v : 0.f);
}

__global__ void bias_mlp(const float* __restrict__ ls,
                         const float* __restrict__ fc1w,
                         const float* __restrict__ fc1b,
                         const float* __restrict__ fc2w) {
    int lane = threadIdx.x & 31;
    int wid = threadIdx.x >> 5;
    if (blockIdx.x == 0 && threadIdx.x < HEADS)
        g_scale[threadIdx.x] = expf(fminf(ls[threadIdx.x], 4.6051702f));
    int e = blockIdx.x * 8 + wid;
    if (e >= 225) return;
    int i = e / 15, j = e % 15;
    float t0 = slog((float)(j - 7));
    float t1 = slog((float)(i - 7));
    float o[6] = {0.f, 0.f, 0.f, 0.f, 0.f, 0.f};
    for (int n = lane; n < 512; n += 32) {
        float hv = fmaxf(t0 * fc1w[n] + t1 * fc1w[512 + n] + fc1b[n], 0.f);
        const float* w2 = fc2w + n * 6;
        #pragma unroll
        for (int c = 0; c < 6; c++) o[c] += hv * w2[c];
    }
    #pragma unroll
    for (int c = 0; c < 6; c++) {
        #pragma unroll
        for (int s = 16; s > 0; s >>= 1) o[c] += __shfl_xor_sync(0xffffffffu, o[c], s);
    }
    if (lane == 0) {
        #pragma unroll
        for (int c = 0; c < 6; c++) g_tab[e * 6 + c] = o[c];
    }
}

__global__ void bias_expand() {
    int e = blockIdx.x * blockDim.x + threadIdx.x;
    int hh = e >> 12;
    int rem = e & 4095;
    int i = rem >> 6, j = rem & 63;
    int dy = (i >> 3) - (j >> 3);
    int dx = (i & 7) - (j & 7);
    float v = g_tab[((dy + 7) * 15 + (dx + 7)) * 6 + hh];
    g_bias[e] = 16.f / (1.f + expf(-v));
}

// ---------------- TF32 GEMM: 64 rows x 192 cols x one matrix per block (R10 core) ----------------
// grid = (3, rtiles) for qkv so q/k/v blocks of the same row-tile are launch-adjacent -> X L2 reuse.
#define GAS_STR 36
#define GBS_STR 200
#define GA_ST (64 * GAS_STR)
#define GB_ST (32 * GBS_STR)
#define G_SMEM ((2 * GA_ST + 2 * GB_ST) * 4)   // 69632 B

// mode: 0 plain+bias (proj), 1 q (+bias,norm,scale,tf32), 2 k (norm,tf32), 3 v (+bias,tf32)
__global__ void __launch_bounds__(256, 3) gemm192(const float* __restrict__ Xin,
                                                  const float* __restrict__ qw,
                                                  const float* __restrict__ kw,
                                                  const float* __restrict__ vw,
                                                  const float* __restrict__ qb,
                                                  const float* __restrict__ vb,
                                                  const float* __restrict__ pw,
                                                  const float* __restrict__ pb,
                                                  float* __restrict__ dout,
                                                  int job) {
    extern __shared__ float sm[];
    float* As = sm;                        // [2][64][GAS_STR]
    float* Bs = sm + 2 * GA_ST;            // [2][32][GBS_STR]
    __shared__ float ssbuf[64][8];
    const uint32_t as_u = smem_u32(As);

    const int tid = threadIdx.x;
    const int lane = tid & 31;
    const int wid = tid >> 5;
    const int wm = wid & 1;                // 2 warps along M (32 rows each)
    const int wn = wid >> 1;               // 4 warps along N (48 cols each)
    const int lr = lane >> 2;
    const int lc = lane & 3;
    const size_t rowbase = (size_t)blockIdx.y * 64;
    const int hb = (wn * 48) >> 5;

    const float* A;
    const float* W;
    const float* bias;
    float* out;
    int mode;
    if (job) {
        A = g_t; W = pw; bias = pb; out = dout; mode = 0;
    } else {
        A = Xin;
        int sel = blockIdx.x;
        mode = sel + 1;
        W = (sel == 0) ? qw : (sel == 1) ? kw : vw;
        bias = (sel == 0) ? qb : (sel == 2) ? vb : (const float*)nullptr;
        out = (sel == 0) ? g_q : (sel == 1) ? g_k : g_v;
    }

    ((float*)ssbuf)[tid] = 0.f;
    ((float*)ssbuf)[256 + tid] = 0.f;

    // 64 rows x 32 floats = 512 float4 = exactly 2 per thread
    auto issueA = [&](int st, int kt) {
        #pragma unroll
        for (int j = 0; j < 2; j++) {
            int id = j * 256 + tid;            // 0..511
            int r = id >> 3, c4 = (id & 7) << 2;
            cp16(as_u + (st * GA_ST + r * GAS_STR + c4) * 4,
                 A + (rowbase + r) * 192 + kt * 32 + c4);
        }
    };

    float4 breg[6];
    auto ldgB = [&](int kt) {
        #pragma unroll
        for (int j = 0; j < 6; j++) {
            int id = j * 256 + tid;
            int r = id / 48, c4 = (id % 48) << 2;
            breg[j] = *(const float4*)(W + (size_t)(kt * 32 + r) * 192 + c4);
        }
    };
    auto stsB = [&](int st) {
        #pragma unroll
        for (int j = 0; j < 6; j++) {
            int id = j * 256 + tid;
            int r = id / 48, c4 = (id % 48) << 2;
            *(float4*)(Bs + st * GB_ST + r * GBS_STR + c4) =
                make_float4(tf32r(breg[j].x), tf32r(breg[j].y),
                            tf32r(breg[j].z), tf32r(breg[j].w));
        }
    };

    issueA(0, 0); cp_commit();
    issueA(1, 1); cp_commit();
    ldgB(0); stsB(0);
    ldgB(1);

    float acc[2][6][4];
    #pragma unroll
    for (int a = 0; a < 2; a++)
        #pragma unroll
        for (int b = 0; b < 6; b++)
            #pragma unroll
            for (int c = 0; c < 4; c++) acc[a][b][c] = 0.f;

    #pragma unroll 1
    for (int kt = 0; kt < 6; kt++) {
        if (kt < 5) cp_wait<1>(); else cp_wait<0>();
        __syncthreads();
        const float* Ab = As + (kt & 1) * GA_ST;
        const float* Bb = Bs + (kt & 1) * GB_ST;
        #pragma unroll
        for (int kk = 0; kk < 32; kk += 8) {
            uint32_t af[2][4];
            #pragma unroll
            for (int ms = 0; ms < 2; ms++) {
                int r0 = wm * 32 + ms * 16 + lr;
                af[ms][0] = f2tf(Ab[r0 * GAS_STR + kk + lc]);
                af[ms][1] = f2tf(Ab[(r0 + 8) * GAS_STR + kk + lc]);
                af[ms][2] = f2tf(Ab[r0 * GAS_STR + kk + lc + 4]);
                af[ms][3] = f2tf(Ab[(r0 + 8) * GAS_STR + kk + lc + 4]);
            }
            #pragma unroll
            for (int ns = 0; ns < 6; ns++) {
                int c0 = wn * 48 + ns * 8 + lr;
                uint32_t bf[2];
                bf[0] = __float_as_uint(Bb[(kk + lc) * GBS_STR + c0]);
                bf[1] = __float_as_uint(Bb[(kk + lc + 4) * GBS_STR + c0]);
                mma8(acc[0][ns], af[0], bf);
                mma8(acc[1][ns], af[1], bf);
            }
        }
        __syncthreads();
        if (kt + 2 < 6) { issueA(kt & 1, kt + 2); cp_commit(); }
        if (kt + 1 < 6) stsB((kt + 1) & 1);
        if (kt + 2 < 6) ldgB(kt + 2);
    }

    // ---- epilogue ----
    if (bias) {
        #pragma unroll
        for (int ms = 0; ms < 2; ms++)
            #pragma unroll
            for (int ns = 0; ns < 6; ns++) {
                int c0 = wn * 48 + ns * 8 + lc * 2;
                float b0 = bias[c0], b1 = bias[c0 + 1];
                acc[ms][ns][0] += b0; acc[ms][ns][1] += b1;
                acc[ms][ns][2] += b0; acc[ms][ns][3] += b1;
            }
    }

    float rs[2][2][2];
    #pragma unroll
    for (int a = 0; a < 2; a++)
        #pragma unroll
        for (int b = 0; b < 2; b++)
            #pragma unroll
            for (int c = 0; c < 2; c++) rs[a][b][c] = 1.f;

    if (mode == 1 || mode == 2) {
        float part[2][2][2];
        #pragma unroll
        for (int a = 0; a < 2; a++)
            #pragma unroll
            for (int b = 0; b < 2; b++)
                #pragma unroll
                for (int c = 0; c < 2; c++) part[a][b][c] = 0.f;
        #pragma unroll
        for (int ms = 0; ms < 2; ms++)
            #pragma unroll
            for (int ns = 0; ns < 6; ns++) {
                int bkt = ((wn * 48 + ns * 8) >> 5) - hb;
                part[ms][0][bkt] += acc[ms][ns][0] * acc[ms][ns][0]
                                  + acc[ms][ns][1] * acc[ms][ns][1];
                part[ms][1][bkt] += acc[ms][ns][2] * acc[ms][ns][2]
                                  + acc[ms][ns][3] * acc[ms][ns][3];
            }
        #pragma unroll
        for (int ms = 0; ms < 2; ms++)
            #pragma unroll
            for (int p = 0; p < 2; p++)
                #pragma unroll
                for (int b = 0; b < 2; b++) {
                    float v = part[ms][p][b];
                    v += __shfl_xor_sync(0xffffffffu, v, 1);
                    v += __shfl_xor_sync(0xffffffffu, v, 2);
                    part[ms][p][b] = v;
                }
        if (lc == 0) {
            #pragma unroll
            for (int ms = 0; ms < 2; ms++)
                #pragma unroll
                for (int p = 0; p < 2; p++)
                    #pragma unroll
                    for (int b = 0; b < 2; b++)
                        atomicAdd(&ssbuf[wm * 32 + ms * 16 + lr + p * 8][hb + b],
                                  part[ms][p][b]);
        }
        __syncthreads();
        #pragma unroll
        for (int ms = 0; ms < 2; ms++)
            #pragma unroll
            for (int p = 0; p < 2; p++)
                #pragma unroll
                for (int b = 0; b < 2; b++) {
                    int row = wm * 32 + ms * 16 + lr + p * 8;
                    float r = rsqrtf(ssbuf[row][hb + b]);
                    if (mode == 1) r *= g_scale[hb + b];
                    rs[ms][p][b] = r;
                }
    }

    #pragma unroll
    for (int ms = 0; ms < 2; ms++) {
        size_t r0 = rowbase + wm * 32 + ms * 16 + lr;
        #pragma unroll
        for (int ns = 0; ns < 6; ns++) {
            int c0 = wn * 48 + ns * 8 + lc * 2;
            int bkt = (c0 >> 5) - hb;
            float o0 = acc[ms][ns][0] * rs[ms][0][bkt];
            float o1 = acc[ms][ns][1] * rs[ms][0][bkt];
            float o2 = acc[ms][ns][2] * rs[ms][1][bkt];
            float o3 = acc[ms][ns][3] * rs[ms][1][bkt];
            if (mode != 0) { o0 = tf32r(o0); o1 = tf32r(o1); o2 = tf32r(o2); o3 = tf32r(o3); }
            *(float2*)(out + r0 * 192 + c0) = make_float2(o0, o1);
            *(float2*)(out + (r0 + 8) * 192 + c0) = make_float2(o2, o3);
        }
    }
}

// ---------------- attention: 4 windows per block (R10 winner, unchanged) ----------------
#define WBUF 7168
#define ATT_SMEM ((2 * WBUF + 64 * 68) * 4)   // 74752 B

__global__ void __launch_bounds__(128) attn_kernel(const float* __restrict__ mask,
                                                   int nW, int WPG) {
    extern __shared__ float sm[];
    const uint32_t sm_u = smem_u32(sm);
    float* Ss = sm + 2 * WBUF;

    const int g = blockIdx.x;
    const int h = blockIdx.y;
    const int tid = threadIdx.x;
    const int lane = tid & 31;
    const int wid = tid >> 5;
    const int lr = lane >> 2;
    const int lc = lane & 3;
    const int m0 = wid * 16;
    const int r0 = m0 + lr, r1 = m0 + lr + 8;

    float bm[8][4];
    {
        const float* bmp = g_bias + h * 4096;
        const float* mkp = mask + (size_t)g * 4096;
        #pragma unroll
        for (int j = 0; j < 8; j++) {
            int c0 = j * 8 + lc * 2;
            float2 b0 = *(const float2*)(bmp + r0 * 64 + c0);
            float2 m0v = *(const float2*)(mkp + r0 * 64 + c0);
            float2 b1 = *(const float2*)(bmp + r1 * 64 + c0);
            float2 m1v = *(const float2*)(mkp + r1 * 64 + c0);
            bm[j][0] = b0.x + m0v.x;
            bm[j][1] = b0.y + m0v.y;
            bm[j][2] = b1.x + m1v.x;
            bm[j][3] = b1.y + m1v.y;
        }
    }

    auto issueW = [&](int st, int w) {
        size_t wbase = (size_t)(g + w * nW) * 64 * 192 + h * 32;
        uint32_t bu = sm_u + st * WBUF * 4;
        #pragma unroll
        for (int j = 0; j < 4; j++) {
            int id = j * 128 + tid;
            int r = id >> 3, c4 = (id & 7) << 2;
            size_t src = wbase + (size_t)r * 192 + c4;
            cp16(bu + (r * 36 + c4) * 4, g_q + src);
            cp16(bu + (2304 + r * 36 + c4) * 4, g_k + src);
            cp16(bu + (4608 + r * 40 + c4) * 4, g_v + src);
        }
    };

    issueW(0, 0); cp_commit();
    if (WPG > 1) { issueW(1, 1); cp_commit(); }

    #pragma unroll 1
    for (int w = 0; w < WPG; w++) {
        if (w + 1 < WPG) cp_wait<1>(); else cp_wait<0>();
        __syncthreads();
        const float* qs = sm + (w & 1) * WBUF;
        const float* ks = qs + 2304;
        const float* vs = qs + 4608;

        float acc[8][4];
        #pragma unroll
        for (int j = 0; j < 8; j++)
            #pragma unroll
            for (int c = 0; c < 4; c++) acc[j][c] = bm[j][c];
        #pragma unroll
        for (int kk = 0; kk < 32; kk += 8) {
            uint32_t af[4];
            af[0] = __float_as_uint(qs[r0 * 36 + kk + lc]);
            af[1] = __float_as_uint(qs[r1 * 36 + kk + lc]);
            af[2] = __float_as_uint(qs[r0 * 36 + kk + lc + 4]);
            af[3] = __float_as_uint(qs[r1 * 36 + kk + lc + 4]);
            #pragma unroll
            for (int j = 0; j < 8; j++) {
                uint32_t bf[2];
                bf[0] = __float_as_uint(ks[(j * 8 + lr) * 36 + kk + lc]);
                bf[1] = __float_as_uint(ks[(j * 8 + lr) * 36 + kk + lc + 4]);
                mma8(acc[j], af, bf);
            }
        }

        float mx0 = -1e30f, mx1 = -1e30f;
        #pragma unroll
        for (int j = 0; j < 8; j++) {
            mx0 = fmaxf(mx0, fmaxf(acc[j][0], acc[j][1]));
            mx1 = fmaxf(mx1, fmaxf(acc[j][2], acc[j][3]));
        }
        mx0 = fmaxf(mx0, __shfl_xor_sync(0xffffffffu, mx0, 1));
        mx0 = fmaxf(mx0, __shfl_xor_sync(0xffffffffu, mx0, 2));
        mx1 = fmaxf(mx1, __shfl_xor_sync(0xffffffffu, mx1, 1));
        mx1 = fmaxf(mx1, __shfl_xor_sync(0xffffffffu, mx1, 2));
        float s0 = 0.f, s1 = 0.f;
        #pragma unroll
        for (int j = 0; j < 8; j++) {
            float e0 = __expf(acc[j][0] - mx0); s0 += e0; acc[j][0] = tf32r(e0);
            float e1 = __expf(acc[j][1] - mx0); s0 += e1; acc[j][1] = tf32r(e1);
            float e2 = __expf(acc[j][2] - mx1); s1 += e2; acc[j][2] = tf32r(e2);
            float e3 = __expf(acc[j][3] - mx1); s1 += e3; acc[j][3] = tf32r(e3);
        }
        s0 += __shfl_xor_sync(0xffffffffu, s0, 1);
        s0 += __shfl_xor_sync(0xffffffffu, s0, 2);
        s1 += __shfl_xor_sync(0xffffffffu, s1, 1);
        s1 += __shfl_xor_sync(0xffffffffu, s1, 2);
        const float inv0 = 1.0f / s0;
        const float inv1 = 1.0f / s1;

        #pragma unroll
        for (int j = 0; j < 8; j++) {
            int c0 = j * 8 + lc * 2;
            *(float2*)&Ss[r0 * 68 + c0] = make_float2(acc[j][0], acc[j][1]);
            *(float2*)&Ss[r1 * 68 + c0] = make_float2(acc[j][2], acc[j][3]);
        }
        __syncwarp();

        float o[4][4];
        #pragma unroll
        for (int j = 0; j < 4; j++)
            #pragma unroll
            for (int c = 0; c < 4; c++) o[j][c] = 0.f;
        #pragma unroll
        for (int kk = 0; kk < 64; kk += 8) {
            uint32_t af[4];
            af[0] = __float_as_uint(Ss[r0 * 68 + kk + lc]);
            af[1] = __float_as_uint(Ss[r1 * 68 + kk + lc]);
            af[2] = __float_as_uint(Ss[r0 * 68 + kk + lc + 4]);
            af[3] = __float_as_uint(Ss[r1 * 68 + kk + lc + 4]);
            #pragma unroll
            for (int j = 0; j < 4; j++) {
                uint32_t bf[2];
                bf[0] = __float_as_uint(vs[(kk + lc) * 40 + j * 8 + lr]);
                bf[1] = __float_as_uint(vs[(kk + lc + 4) * 40 + j * 8 + lr]);
                mma8(o[j], af, bf);
            }
        }
        size_t obase = (size_t)(g + w * nW) * 64 * 192 + h * 32;
        #pragma unroll
        for (int j = 0; j < 4; j++) {
            int c0 = j * 8 + lc * 2;
            *(float2*)(g_t + obase + (size_t)r0 * 192 + c0) =
                make_float2(o[j][0] * inv0, o[j][1] * inv0);
            *(float2*)(g_t + obase + (size_t)r1 * 192 + c0) =
                make_float2(o[j][2] * inv1, o[j][3] * inv1);
        }

        __syncthreads();
        if (w + 2 < WPG) { issueW(w & 1, w + 2); cp_commit(); }
    }
}

// ---------------- launch ----------------
extern "C" void kernel_launch(void* const* d_in, const int* in_sizes, int n_in,
                              void* d_out, int out_size) {
    const float* hidden = (const float*)d_in[0];
    const float* mask   = (const float*)d_in[1];
    const float* ls     = (const float*)d_in[2];
    const float* fc1w   = (const float*)d_in[3];
    const float* fc1b   = (const float*)d_in[4];
    const float* fc2w   = (const float*)d_in[5];
    const float* qw     = (const float*)d_in[6];
    const float* qb     = (const float*)d_in[7];
    const float* kw     = (const float*)d_in[8];
    const float* vw     = (const float*)d_in[9];
    const float* vb     = (const float*)d_in[10];
    const float* pw     = (const float*)d_in[11];
    const float* pb     = (const float*)d_in[12];
    float* out = (float*)d_out;

    int B  = in_sizes[0] / (64 * 192);
    int nW = in_sizes[1] / (64 * 64);
    int WPG = B / nW;
    int rtiles = B;

    cudaFuncSetAttribute(gemm192, cudaFuncAttributeMaxDynamicSharedMemorySize, G_SMEM);
    cudaFuncSetAttribute(attn_kernel, cudaFuncAttributeMaxDynamicSharedMemorySize, ATT_SMEM);

    bias_mlp<<<29, 256>>>(ls, fc1w, fc1b, fc2w);
    bias_expand<<<48, 512>>>();
    gemm192<<<dim3(3, rtiles), 256, G_SMEM>>>(hidden, qw, kw, vw, qb, vb, pw, pb, out, 0);
    attn_kernel<<<dim3(nW, HEADS), 128, ATT_SMEM>>>(mask, nW, WPG);
    gemm192<<<dim3(1, rtiles), 256, G_SMEM>>>(hidden, qw, kw, vw, qb, vb, pw, pb, out, 1);
}

// round 14
// speedup vs baseline: 1.2915x; 1.2915x over previous
#include <cuda_runtime.h>
#include <cstdint>
#include <math.h>

#define HEADS 6
static constexpr size_t MAXELEM = (size_t)4096 * 64 * 192;

__device__ float g_q[MAXELEM];
__device__ float g_k[MAXELEM];
__device__ float g_v[MAXELEM];
__device__ float g_t[MAXELEM];
__device__ float g_bias[HEADS * 64 * 64];
__device__ float g_scale[HEADS];
__device__ float g_tab[225 * 6];

// ---------------- helpers ----------------
__device__ __forceinline__ uint32_t f2tf(float x) {
    uint32_t u;
    asm("cvt.rna.tf32.f32 %0, %1;" : "=r"(u) : "f"(x));
    return u;
}
__device__ __forceinline__ float tf32r(float x) { return __uint_as_float(f2tf(x)); }

__device__ __forceinline__ void mma8(float c[4], const uint32_t a[4], const uint32_t b[2]) {
    asm volatile(
        "mma.sync.aligned.m16n8k8.row.col.f32.tf32.tf32.f32 "
        "{%0,%1,%2,%3}, {%4,%5,%6,%7}, {%8,%9}, {%0,%1,%2,%3};"
        : "+f"(c[0]), "+f"(c[1]), "+f"(c[2]), "+f"(c[3])
        : "r"(a[0]), "r"(a[1]), "r"(a[2]), "r"(a[3]), "r"(b[0]), "r"(b[1]));
}

__device__ __forceinline__ uint32_t smem_u32(const void* p) {
    uint32_t a;
    asm("{ .reg .u64 t; cvta.to.shared.u64 t, %1; cvt.u32.u64 %0, t; }" : "=r"(a) : "l"(p));
    return a;
}
__device__ __forceinline__ void cp16(uint32_t dst, const void* src) {
    asm volatile("cp.async.cg.shared.global [%0], [%1], 16;" :: "r"(dst), "l"(src) : "memory");
}
__device__ __forceinline__ void cp_commit() {
    asm volatile("cp.async.commit_group;" ::: "memory");
}
template <int N>
__device__ __forceinline__ void cp_wait() {
    asm volatile("cp.async.wait_group %0;" :: "n"(N) : "memory");
}

// ---------------- bias / scale precompute (parallel) ----------------
__device__ __forceinline__ float slog(float d) {
    float x = d * (8.0f / 7.0f);
    float a = fabsf(x);
    float v = log2f(a + 1.0f) * (1.0f / 3.0f);
    return (x > 0.f) ? v : ((x < 0.f) ? -v : 0.f);
}

__global__ void bias_mlp(const float* __restrict__ ls,
                         const float* __restrict__ fc1w,
                         const float* __restrict__ fc1b,
                         const float* __restrict__ fc2w) {
    int lane = threadIdx.x & 31;
    int wid = threadIdx.x >> 5;
    if (blockIdx.x == 0 && threadIdx.x < HEADS)
        g_scale[threadIdx.x] = expf(fminf(ls[threadIdx.x], 4.6051702f));
    int e = blockIdx.x * 8 + wid;
    if (e >= 225) return;
    int i = e / 15, j = e % 15;
    float t0 = slog((float)(j - 7));
    float t1 = slog((float)(i - 7));
    float o[6] = {0.f, 0.f, 0.f, 0.f, 0.f, 0.f};
    for (int n = lane; n < 512; n += 32) {
        float hv = fmaxf(t0 * fc1w[n] + t1 * fc1w[512 + n] + fc1b[n], 0.f);
        const float* w2 = fc2w + n * 6;
        #pragma unroll
        for (int c = 0; c < 6; c++) o[c] += hv * w2[c];
    }
    #pragma unroll
    for (int c = 0; c < 6; c++) {
        #pragma unroll
        for (int s = 16; s > 0; s >>= 1) o[c] += __shfl_xor_sync(0xffffffffu, o[c], s);
    }
    if (lane == 0) {
        #pragma unroll
        for (int c = 0; c < 6; c++) g_tab[e * 6 + c] = o[c];
    }
}

__global__ void bias_expand() {
    int e = blockIdx.x * blockDim.x + threadIdx.x;
    int hh = e >> 12;
    int rem = e & 4095;
    int i = rem >> 6, j = rem & 63;
    int dy = (i >> 3) - (j >> 3);
    int dx = (i & 7) - (j & 7);
    float v = g_tab[((dy + 7) * 15 + (dx + 7)) * 6 + hh];
    g_bias[e] = 16.f / (1.f + expf(-v));
}

// ---------------- TF32 GEMM: 64 rows x 192 cols x one matrix per block (R10 core) ----------------
// grid = (3, rtiles) for qkv: q/k/v blocks of a row-tile are launch-adjacent -> X served from L2.
#define GAS_STR 36
#define GBS_STR 200
#define GA_ST (64 * GAS_STR)
#define GB_ST (32 * GBS_STR)
#define G_SMEM ((2 * GA_ST + 2 * GB_ST) * 4)   // 69632 B

// mode: 0 plain+bias (proj), 1 q (+bias,norm,scale,tf32), 2 k (norm,tf32), 3 v (+bias,tf32)
__global__ void __launch_bounds__(256, 2) gemm192(const float* __restrict__ Xin,
                                                  const float* __restrict__ qw,
                                                  const float* __restrict__ kw,
                                                  const float* __restrict__ vw,
                                                  const float* __restrict__ qb,
                                                  const float* __restrict__ vb,
                                                  const float* __restrict__ pw,
                                                  const float* __restrict__ pb,
                                                  float* __restrict__ dout,
                                                  int job) {
    extern __shared__ float sm[];
    float* As = sm;                        // [2][64][GAS_STR]
    float* Bs = sm + 2 * GA_ST;            // [2][32][GBS_STR]
    __shared__ float ssbuf[64][8];
    const uint32_t as_u = smem_u32(As);

    const int tid = threadIdx.x;
    const int lane = tid & 31;
    const int wid = tid >> 5;
    const int wm = wid & 1;                // 2 warps along M (32 rows each)
    const int wn = wid >> 1;               // 4 warps along N (48 cols each)
    const int lr = lane >> 2;
    const int lc = lane & 3;
    const size_t rowbase = (size_t)blockIdx.y * 64;
    const int hb = (wn * 48) >> 5;

    const float* A;
    const float* W;
    const float* bias;
    float* out;
    int mode;
    if (job) {
        A = g_t; W = pw; bias = pb; out = dout; mode = 0;
    } else {
        A = Xin;
        int sel = blockIdx.x;
        mode = sel + 1;
        W = (sel == 0) ? qw : (sel == 1) ? kw : vw;
        bias = (sel == 0) ? qb : (sel == 2) ? vb : (const float*)nullptr;
        out = (sel == 0) ? g_q : (sel == 1) ? g_k : g_v;
    }

    ((float*)ssbuf)[tid] = 0.f;
    ((float*)ssbuf)[256 + tid] = 0.f;

    // 64 rows x 32 floats = 512 float4 = exactly 2 per thread
    auto issueA = [&](int st, int kt) {
        #pragma unroll
        for (int j = 0; j < 2; j++) {
            int id = j * 256 + tid;            // 0..511
            int r = id >> 3, c4 = (id & 7) << 2;
            cp16(as_u + (st * GA_ST + r * GAS_STR + c4) * 4,
                 A + (rowbase + r) * 192 + kt * 32 + c4);
        }
    };

    float4 breg[6];
    auto ldgB = [&](int kt) {
        #pragma unroll
        for (int j = 0; j < 6; j++) {
            int id = j * 256 + tid;
            int r = id / 48, c4 = (id % 48) << 2;
            breg[j] = *(const float4*)(W + (size_t)(kt * 32 + r) * 192 + c4);
        }
    };
    auto stsB = [&](int st) {
        #pragma unroll
        for (int j = 0; j < 6; j++) {
            int id = j * 256 + tid;
            int r = id / 48, c4 = (id % 48) << 2;
            *(float4*)(Bs + st * GB_ST + r * GBS_STR + c4) =
                make_float4(tf32r(breg[j].x), tf32r(breg[j].y),
                            tf32r(breg[j].z), tf32r(breg[j].w));
        }
    };

    issueA(0, 0); cp_commit();
    issueA(1, 1); cp_commit();
    ldgB(0); stsB(0);
    ldgB(1);

    float acc[2][6][4];
    #pragma unroll
    for (int a = 0; a < 2; a++)
        #pragma unroll
        for (int b = 0; b < 6; b++)
            #pragma unroll
            for (int c = 0; c < 4; c++) acc[a][b][c] = 0.f;

    #pragma unroll 1
    for (int kt = 0; kt < 6; kt++) {
        if (kt < 5) cp_wait<1>(); else cp_wait<0>();
        __syncthreads();
        const float* Ab = As + (kt & 1) * GA_ST;
        const float* Bb = Bs + (kt & 1) * GB_ST;
        #pragma unroll
        for (int kk = 0; kk < 32; kk += 8) {
            uint32_t af[2][4];
            #pragma unroll
            for (int ms = 0; ms < 2; ms++) {
                int r0 = wm * 32 + ms * 16 + lr;
                af[ms][0] = f2tf(Ab[r0 * GAS_STR + kk + lc]);
                af[ms][1] = f2tf(Ab[(r0 + 8) * GAS_STR + kk + lc]);
                af[ms][2] = f2tf(Ab[r0 * GAS_STR + kk + lc + 4]);
                af[ms][3] = f2tf(Ab[(r0 + 8) * GAS_STR + kk + lc + 4]);
            }
            #pragma unroll
            for (int ns = 0; ns < 6; ns++) {
                int c0 = wn * 48 + ns * 8 + lr;
                uint32_t bf[2];
                bf[0] = __float_as_uint(Bb[(kk + lc) * GBS_STR + c0]);
                bf[1] = __float_as_uint(Bb[(kk + lc + 4) * GBS_STR + c0]);
                mma8(acc[0][ns], af[0], bf);
                mma8(acc[1][ns], af[1], bf);
            }
        }
        __syncthreads();
        if (kt + 2 < 6) { issueA(kt & 1, kt + 2); cp_commit(); }
        if (kt + 1 < 6) stsB((kt + 1) & 1);
        if (kt + 2 < 6) ldgB(kt + 2);
    }

    // ---- epilogue ----
    if (bias) {
        #pragma unroll
        for (int ms = 0; ms < 2; ms++)
            #pragma unroll
            for (int ns = 0; ns < 6; ns++) {
                int c0 = wn * 48 + ns * 8 + lc * 2;
                float b0 = bias[c0], b1 = bias[c0 + 1];
                acc[ms][ns][0] += b0; acc[ms][ns][1] += b1;
                acc[ms][ns][2] += b0; acc[ms][ns][3] += b1;
            }
    }

    float rs[2][2][2];
    #pragma unroll
    for (int a = 0; a < 2; a++)
        #pragma unroll
        for (int b = 0; b < 2; b++)
            #pragma unroll
            for (int c = 0; c < 2; c++) rs[a][b][c] = 1.f;

    if (mode == 1 || mode == 2) {
        float part[2][2][2];
        #pragma unroll
        for (int a = 0; a < 2; a++)
            #pragma unroll
            for (int b = 0; b < 2; b++)
                #pragma unroll
                for (int c = 0; c < 2; c++) part[a][b][c] = 0.f;
        #pragma unroll
        for (int ms = 0; ms < 2; ms++)
            #pragma unroll
            for (int ns = 0; ns < 6; ns++) {
                int bkt = ((wn * 48 + ns * 8) >> 5) - hb;
                part[ms][0][bkt] += acc[ms][ns][0] * acc[ms][ns][0]
                                  + acc[ms][ns][1] * acc[ms][ns][1];
                part[ms][1][bkt] += acc[ms][ns][2] * acc[ms][ns][2]
                                  + acc[ms][ns][3] * acc[ms][ns][3];
            }
        #pragma unroll
        for (int ms = 0; ms < 2; ms++)
            #pragma unroll
            for (int p = 0; p < 2; p++)
                #pragma unroll
                for (int b = 0; b < 2; b++) {
                    float v = part[ms][p][b];
                    v += __shfl_xor_sync(0xffffffffu, v, 1);
                    v += __shfl_xor_sync(0xffffffffu, v, 2);
                    part[ms][p][b] = v;
                }
        if (lc == 0) {
            #pragma unroll
            for (int ms = 0; ms < 2; ms++)
                #pragma unroll
                for (int p = 0; p < 2; p++)
                    #pragma unroll
                    for (int b = 0; b < 2; b++)
                        atomicAdd(&ssbuf[wm * 32 + ms * 16 + lr + p * 8][hb + b],
                                  part[ms][p][b]);
        }
        __syncthreads();
        #pragma unroll
        for (int ms = 0; ms < 2; ms++)
            #pragma unroll
            for (int p = 0; p < 2; p++)
                #pragma unroll
                for (int b = 0; b < 2; b++) {
                    int row = wm * 32 + ms * 16 + lr + p * 8;
                    float r = rsqrtf(ssbuf[row][hb + b]);
                    if (mode == 1) r *= g_scale[hb + b];
                    rs[ms][p][b] = r;
                }
    }

    #pragma unroll
    for (int ms = 0; ms < 2; ms++) {
        size_t r0 = rowbase + wm * 32 + ms * 16 + lr;
        #pragma unroll
        for (int ns = 0; ns < 6; ns++) {
            int c0 = wn * 48 + ns * 8 + lc * 2;
            int bkt = (c0 >> 5) - hb;
            float o0 = acc[ms][ns][0] * rs[ms][0][bkt];
            float o1 = acc[ms][ns][1] * rs[ms][0][bkt];
            float o2 = acc[ms][ns][2] * rs[ms][1][bkt];
            float o3 = acc[ms][ns][3] * rs[ms][1][bkt];
            if (mode != 0) { o0 = tf32r(o0); o1 = tf32r(o1); o2 = tf32r(o2); o3 = tf32r(o3); }
            *(float2*)(out + r0 * 192 + c0) = make_float2(o0, o1);
            *(float2*)(out + (r0 + 8) * 192 + c0) = make_float2(o2, o3);
        }
    }
}

// ---------------- attention: 4 windows per block (R10 winner, unchanged) ----------------
#define WBUF 7168
#define ATT_SMEM ((2 * WBUF + 64 * 68) * 4)   // 74752 B

__global__ void __launch_bounds__(128) attn_kernel(const float* __restrict__ mask,
                                                   int nW, int WPG) {
    extern __shared__ float sm[];
    const uint32_t sm_u = smem_u32(sm);
    float* Ss = sm + 2 * WBUF;

    const int g = blockIdx.x;
    const int h = blockIdx.y;
    const int tid = threadIdx.x;
    const int lane = tid & 31;
    const int wid = tid >> 5;
    const int lr = lane >> 2;
    const int lc = lane & 3;
    const int m0 = wid * 16;
    const int r0 = m0 + lr, r1 = m0 + lr + 8;

    float bm[8][4];
    {
        const float* bmp = g_bias + h * 4096;
        const float* mkp = mask + (size_t)g * 4096;
        #pragma unroll
        for (int j = 0; j < 8; j++) {
            int c0 = j * 8 + lc * 2;
            float2 b0 = *(const float2*)(bmp + r0 * 64 + c0);
            float2 m0v = *(const float2*)(mkp + r0 * 64 + c0);
            float2 b1 = *(const float2*)(bmp + r1 * 64 + c0);
            float2 m1v = *(const float2*)(mkp + r1 * 64 + c0);
            bm[j][0] = b0.x + m0v.x;
            bm[j][1] = b0.y + m0v.y;
            bm[j][2] = b1.x + m1v.x;
            bm[j][3] = b1.y + m1v.y;
        }
    }

    auto issueW = [&](int st, int w) {
        size_t wbase = (size_t)(g + w * nW) * 64 * 192 + h * 32;
        uint32_t bu = sm_u + st * WBUF * 4;
        #pragma unroll
        for (int j = 0; j < 4; j++) {
            int id = j * 128 + tid;
            int r = id >> 3, c4 = (id & 7) << 2;
            size_t src = wbase + (size_t)r * 192 + c4;
            cp16(bu + (r * 36 + c4) * 4, g_q + src);
            cp16(bu + (2304 + r * 36 + c4) * 4, g_k + src);
            cp16(bu + (4608 + r * 40 + c4) * 4, g_v + src);
        }
    };

    issueW(0, 0); cp_commit();
    if (WPG > 1) { issueW(1, 1); cp_commit(); }

    #pragma unroll 1
    for (int w = 0; w < WPG; w++) {
        if (w + 1 < WPG) cp_wait<1>(); else cp_wait<0>();
        __syncthreads();
        const float* qs = sm + (w & 1) * WBUF;
        const float* ks = qs + 2304;
        const float* vs = qs + 4608;

        float acc[8][4];
        #pragma unroll
        for (int j = 0; j < 8; j++)
            #pragma unroll
            for (int c = 0; c < 4; c++) acc[j][c] = bm[j][c];
        #pragma unroll
        for (int kk = 0; kk < 32; kk += 8) {
            uint32_t af[4];
            af[0] = __float_as_uint(qs[r0 * 36 + kk + lc]);
            af[1] = __float_as_uint(qs[r1 * 36 + kk + lc]);
            af[2] = __float_as_uint(qs[r0 * 36 + kk + lc + 4]);
            af[3] = __float_as_uint(qs[r1 * 36 + kk + lc + 4]);
            #pragma unroll
            for (int j = 0; j < 8; j++) {
                uint32_t bf[2];
                bf[0] = __float_as_uint(ks[(j * 8 + lr) * 36 + kk + lc]);
                bf[1] = __float_as_uint(ks[(j * 8 + lr) * 36 + kk + lc + 4]);
                mma8(acc[j], af, bf);
            }
        }

        float mx0 = -1e30f, mx1 = -1e30f;
        #pragma unroll
        for (int j = 0; j < 8; j++) {
            mx0 = fmaxf(mx0, fmaxf(acc[j][0], acc[j][1]));
            mx1 = fmaxf(mx1, fmaxf(acc[j][2], acc[j][3]));
        }
        mx0 = fmaxf(mx0, __shfl_xor_sync(0xffffffffu, mx0, 1));
        mx0 = fmaxf(mx0, __shfl_xor_sync(0xffffffffu, mx0, 2));
        mx1 = fmaxf(mx1, __shfl_xor_sync(0xffffffffu, mx1, 1));
        mx1 = fmaxf(mx1, __shfl_xor_sync(0xffffffffu, mx1, 2));
        float s0 = 0.f, s1 = 0.f;
        #pragma unroll
        for (int j = 0; j < 8; j++) {
            float e0 = __expf(acc[j][0] - mx0); s0 += e0; acc[j][0] = tf32r(e0);
            float e1 = __expf(acc[j][1] - mx0); s0 += e1; acc[j][1] = tf32r(e1);
            float e2 = __expf(acc[j][2] - mx1); s1 += e2; acc[j][2] = tf32r(e2);
            float e3 = __expf(acc[j][3] - mx1); s1 += e3; acc[j][3] = tf32r(e3);
        }
        s0 += __shfl_xor_sync(0xffffffffu, s0, 1);
        s0 += __shfl_xor_sync(0xffffffffu, s0, 2);
        s1 += __shfl_xor_sync(0xffffffffu, s1, 1);
        s1 += __shfl_xor_sync(0xffffffffu, s1, 2);
        const float inv0 = 1.0f / s0;
        const float inv1 = 1.0f / s1;

        #pragma unroll
        for (int j = 0; j < 8; j++) {
            int c0 = j * 8 + lc * 2;
            *(float2*)&Ss[r0 * 68 + c0] = make_float2(acc[j][0], acc[j][1]);
            *(float2*)&Ss[r1 * 68 + c0] = make_float2(acc[j][2], acc[j][3]);
        }
        __syncwarp();

        float o[4][4];
        #pragma unroll
        for (int j = 0; j < 4; j++)
            #pragma unroll
            for (int c = 0; c < 4; c++) o[j][c] = 0.f;
        #pragma unroll
        for (int kk = 0; kk < 64; kk += 8) {
            uint32_t af[4];
            af[0] = __float_as_uint(Ss[r0 * 68 + kk + lc]);
            af[1] = __float_as_uint(Ss[r1 * 68 + kk + lc]);
            af[2] = __float_as_uint(Ss[r0 * 68 + kk + lc + 4]);
            af[3] = __float_as_uint(Ss[r1 * 68 + kk + lc + 4]);
            #pragma unroll
            for (int j = 0; j < 4; j++) {
                uint32_t bf[2];
                bf[0] = __float_as_uint(vs[(kk + lc) * 40 + j * 8 + lr]);
                bf[1] = __float_as_uint(vs[(kk + lc + 4) * 40 + j * 8 + lr]);
                mma8(o[j], af, bf);
            }
        }
        size_t obase = (size_t)(g + w * nW) * 64 * 192 + h * 32;
        #pragma unroll
        for (int j = 0; j < 4; j++) {
            int c0 = j * 8 + lc * 2;
            *(float2*)(g_t + obase + (size_t)r0 * 192 + c0) =
                make_float2(o[j][0] * inv0, o[j][1] * inv0);
            *(float2*)(g_t + obase + (size_t)r1 * 192 + c0) =
                make_float2(o[j][2] * inv1, o[j][3] * inv1);
        }

        __syncthreads();
        if (w + 2 < WPG) { issueW(w & 1, w + 2); cp_commit(); }
    }
}

// ---------------- launch ----------------
extern "C" void kernel_launch(void* const* d_in, const int* in_sizes, int n_in,
                              void* d_out, int out_size) {
    const float* hidden = (const float*)d_in[0];
    const float* mask   = (const float*)d_in[1];
    const float* ls     = (const float*)d_in[2];
    const float* fc1w   = (const float*)d_in[3];
    const float* fc1b   = (const float*)d_in[4];
    const float* fc2w   = (const float*)d_in[5];
    const float* qw     = (const float*)d_in[6];
    const float* qb     = (const float*)d_in[7];
    const float* kw     = (const float*)d_in[8];
    const float* vw     = (const float*)d_in[9];
    const float* vb     = (const float*)d_in[10];
    const float* pw     = (const float*)d_in[11];
    const float* pb     = (const float*)d_in[12];
    float* out = (float*)d_out;

    int B  = in_sizes[0] / (64 * 192);
    int nW = in_sizes[1] / (64 * 64);
    int WPG = B / nW;
    int rtiles = B;

    cudaFuncSetAttribute(gemm192, cudaFuncAttributeMaxDynamicSharedMemorySize, G_SMEM);
    cudaFuncSetAttribute(attn_kernel, cudaFuncAttributeMaxDynamicSharedMemorySize, ATT_SMEM);

    bias_mlp<<<29, 256>>>(ls, fc1w, fc1b, fc2w);
    bias_expand<<<48, 512>>>();
    gemm192<<<dim3(3, rtiles), 256, G_SMEM>>>(hidden, qw, kw, vw, qb, vb, pw, pb, out, 0);
    attn_kernel<<<dim3(nW, HEADS), 128, ATT_SMEM>>>(mask, nW, WPG);
    gemm192<<<dim3(1, rtiles), 256, G_SMEM>>>(hidden, qw, kw, vw, qb, vb, pw, pb, out, 1);
}

// round 15
// speedup vs baseline: 1.4230x; 1.1018x over previous
#include <cuda_runtime.h>
#include <cstdint>
#include <math.h>

#define HEADS 6
static constexpr size_t MAXELEM = (size_t)4096 * 64 * 192;

__device__ float g_q[MAXELEM];
__device__ float g_k[MAXELEM];
__device__ float g_v[MAXELEM];
__device__ float g_t[MAXELEM];
__device__ float g_bias[HEADS * 64 * 64];
__device__ float g_scale[HEADS];
__device__ float g_tab[225 * 6];

// ---------------- helpers ----------------
__device__ __forceinline__ uint32_t f2tf(float x) {
    uint32_t u;
    asm("cvt.rna.tf32.f32 %0, %1;" : "=r"(u) : "f"(x));
    return u;
}
__device__ __forceinline__ float tf32r(float x) { return __uint_as_float(f2tf(x)); }

__device__ __forceinline__ void mma8(float c[4], const uint32_t a[4], const uint32_t b[2]) {
    asm volatile(
        "mma.sync.aligned.m16n8k8.row.col.f32.tf32.tf32.f32 "
        "{%0,%1,%2,%3}, {%4,%5,%6,%7}, {%8,%9}, {%0,%1,%2,%3};"
        : "+f"(c[0]), "+f"(c[1]), "+f"(c[2]), "+f"(c[3])
        : "r"(a[0]), "r"(a[1]), "r"(a[2]), "r"(a[3]), "r"(b[0]), "r"(b[1]));
}

__device__ __forceinline__ uint32_t smem_u32(const void* p) {
    uint32_t a;
    asm("{ .reg .u64 t; cvta.to.shared.u64 t, %1; cvt.u32.u64 %0, t; }" : "=r"(a) : "l"(p));
    return a;
}
__device__ __forceinline__ void cp16(uint32_t dst, const void* src) {
    asm volatile("cp.async.cg.shared.global [%0], [%1], 16;" :: "r"(dst), "l"(src) : "memory");
}
__device__ __forceinline__ void cp_commit() {
    asm volatile("cp.async.commit_group;" ::: "memory");
}
template <int N>
__device__ __forceinline__ void cp_wait() {
    asm volatile("cp.async.wait_group %0;" :: "n"(N) : "memory");
}

// ---------------- bias / scale precompute (parallel) ----------------
__device__ __forceinline__ float slog(float d) {
    float x = d * (8.0f / 7.0f);
    float a = fabsf(x);
    float v = log2f(a + 1.0f) * (1.0f / 3.0f);
    return (x > 0.f) ? v : ((x < 0.f) ? -v : 0.f);
}

__global__ void bias_mlp(const float* __restrict__ ls,
                         const float* __restrict__ fc1w,
                         const float* __restrict__ fc1b,
                         const float* __restrict__ fc2w) {
    int lane = threadIdx.x & 31;
    int wid = threadIdx.x >> 5;
    if (blockIdx.x == 0 && threadIdx.x < HEADS)
        g_scale[threadIdx.x] = expf(fminf(ls[threadIdx.x], 4.6051702f));
    int e = blockIdx.x * 8 + wid;
    if (e >= 225) return;
    int i = e / 15, j = e % 15;
    float t0 = slog((float)(j - 7));
    float t1 = slog((float)(i - 7));
    float o[6] = {0.f, 0.f, 0.f, 0.f, 0.f, 0.f};
    for (int n = lane; n < 512; n += 32) {
        float hv = fmaxf(t0 * fc1w[n] + t1 * fc1w[512 + n] + fc1b[n], 0.f);
        const float* w2 = fc2w + n * 6;
        #pragma unroll
        for (int c = 0; c < 6; c++) o[c] += hv * w2[c];
    }
    #pragma unroll
    for (int c = 0; c < 6; c++) {
        #pragma unroll
        for (int s = 16; s > 0; s >>= 1) o[c] += __shfl_xor_sync(0xffffffffu, o[c], s);
    }
    if (lane == 0) {
        #pragma unroll
        for (int c = 0; c < 6; c++) g_tab[e * 6 + c] = o[c];
    }
}

__global__ void bias_expand() {
    int e = blockIdx.x * blockDim.x + threadIdx.x;
    int hh = e >> 12;
    int rem = e & 4095;
    int i = rem >> 6, j = rem & 63;
    int dy = (i >> 3) - (j >> 3);
    int dx = (i & 7) - (j & 7);
    float v = g_tab[((dy + 7) * 15 + (dx + 7)) * 6 + hh];
    g_bias[e] = 16.f / (1.f + expf(-v));
}

// ---------------- pipelined TF32 GEMM (R4 winner): one 128x64 tile per block ----------------
#define AS_STR 36   // 36 % 32 == 4 -> lr*36+lc covers 32 distinct banks
#define BS_STR 72   // lc*72+lr covers 32 distinct banks
#define A_ST (128 * AS_STR)          // floats per A stage
#define B_ST (32 * BS_STR)           // floats per B stage
#define GEMM_SMEM ((2 * A_ST + 2 * B_ST) * 4)   // 55296 B

// mode: 0 = +bias (proj/out), 1 = +bias,L2norm,*scale,tf32 (q),
//       2 = L2norm,tf32 (k), 3 = +bias,tf32 (v)
__global__ void __launch_bounds__(256) gemm_kernel(const float* __restrict__ Xin,
                                                   const float* __restrict__ qw,
                                                   const float* __restrict__ kw,
                                                   const float* __restrict__ vw,
                                                   const float* __restrict__ qb,
                                                   const float* __restrict__ vb,
                                                   const float* __restrict__ pw,
                                                   const float* __restrict__ pb,
                                                   float* __restrict__ dout,
                                                   int job) {
    extern __shared__ float sm[];
    float* As = sm;                 // [2][128][AS_STR]
    float* Bs = sm + 2 * A_ST;      // [2][32][BS_STR]
    const uint32_t as_u = smem_u32(sm);
    const uint32_t bs_u = as_u + 2 * A_ST * 4;

    const int tid = threadIdx.x;
    const int lane = tid & 31;
    const int wid = tid >> 5;
    const int wm = wid & 3;
    const int wn = wid >> 2;
    const int lr = lane >> 2;
    const int lc = lane & 3;
    const size_t rowbase = (size_t)blockIdx.x * 128;

    int coloff, mode;
    const float *A, *W, *bias;
    float* out;
    if (job) {
        A = g_t; W = pw; bias = pb; out = dout;
        coloff = blockIdx.y * 64; mode = 0;
    } else {
        A = Xin;
        int sel = blockIdx.y / 3;
        coloff = (blockIdx.y % 3) * 64;
        mode = sel + 1;
        W = (sel == 0) ? qw : (sel == 1) ? kw : vw;
        bias = (sel == 0) ? qb : (sel == 2) ? vb : (const float*)nullptr;
        out = (sel == 0) ? g_q : (sel == 1) ? g_k : g_v;
    }

    // async stage loaders
    auto issueA = [&](int st, int kt) {
        #pragma unroll
        for (int j = 0; j < 4; j++) {
            int id = j * 256 + tid;            // 0..1023
            int r = id >> 3;
            int ch = (id & 7) << 2;            // float col 0..28
            cp16(as_u + (st * A_ST + r * AS_STR + ch) * 4,
                 A + (rowbase + r) * 192 + kt * 32 + ch);
        }
    };
    auto issueB = [&](int st, int kt) {
        #pragma unroll
        for (int j = 0; j < 2; j++) {
            int id = j * 256 + tid;            // 0..511
            int r = id >> 4;
            int ch = (id & 15) << 2;           // float col 0..60
            cp16(bs_u + (st * B_ST + r * BS_STR + ch) * 4,
                 W + (size_t)(kt * 32 + r) * 192 + coloff + ch);
        }
    };

    float acc[2][4][4];
    #pragma unroll
    for (int a = 0; a < 2; a++)
        #pragma unroll
        for (int b = 0; b < 4; b++)
            #pragma unroll
            for (int c = 0; c < 4; c++) acc[a][b][c] = 0.f;

    issueA(0, 0); issueB(0, 0); cp_commit();
    issueA(1, 1); issueB(1, 1); cp_commit();

    #pragma unroll 1
    for (int kt = 0; kt < 6; kt++) {
        if (kt < 5) cp_wait<1>(); else cp_wait<0>();
        __syncthreads();
        const float* Ab = As + (kt & 1) * A_ST;
        const float* Bb = Bs + (kt & 1) * B_ST;
        #pragma unroll
        for (int kk = 0; kk < 32; kk += 8) {
            uint32_t af[2][4];
            #pragma unroll
            for (int ms = 0; ms < 2; ms++) {
                int r0 = wm * 32 + ms * 16 + lr;
                af[ms][0] = f2tf(Ab[r0 * AS_STR + kk + lc]);
                af[ms][1] = f2tf(Ab[(r0 + 8) * AS_STR + kk + lc]);
                af[ms][2] = f2tf(Ab[r0 * AS_STR + kk + lc + 4]);
                af[ms][3] = f2tf(Ab[(r0 + 8) * AS_STR + kk + lc + 4]);
            }
            #pragma unroll
            for (int ns = 0; ns < 4; ns++) {
                int c0 = wn * 32 + ns * 8 + lr;
                uint32_t bf[2];
                bf[0] = f2tf(Bb[(kk + lc) * BS_STR + c0]);
                bf[1] = f2tf(Bb[(kk + lc + 4) * BS_STR + c0]);
                mma8(acc[0][ns], af[0], bf);
                mma8(acc[1][ns], af[1], bf);
            }
        }
        __syncthreads();
        if (kt + 2 < 6) { issueA(kt & 1, kt + 2); issueB(kt & 1, kt + 2); cp_commit(); }
    }

    // epilogue
    float scl = (mode == 1) ? g_scale[(coloff >> 5) + wn] : 1.f;
    #pragma unroll
    for (int ms = 0; ms < 2; ms++) {
        float vv[4][4];
        float ssa = 0.f, ssb = 0.f;
        #pragma unroll
        for (int ns = 0; ns < 4; ns++) {
            int c0 = coloff + wn * 32 + ns * 8 + lc * 2;
            float b0 = bias ? bias[c0] : 0.f;
            float b1 = bias ? bias[c0 + 1] : 0.f;
            vv[ns][0] = acc[ms][ns][0] + b0;
            vv[ns][1] = acc[ms][ns][1] + b1;
            vv[ns][2] = acc[ms][ns][2] + b0;
            vv[ns][3] = acc[ms][ns][3] + b1;
            ssa += vv[ns][0] * vv[ns][0] + vv[ns][1] * vv[ns][1];
            ssb += vv[ns][2] * vv[ns][2] + vv[ns][3] * vv[ns][3];
        }
        float ra = 1.f, rb = 1.f;
        if (mode == 1 || mode == 2) {
            ssa += __shfl_xor_sync(0xffffffffu, ssa, 1);
            ssa += __shfl_xor_sync(0xffffffffu, ssa, 2);
            ssb += __shfl_xor_sync(0xffffffffu, ssb, 1);
            ssb += __shfl_xor_sync(0xffffffffu, ssb, 2);
            ra = rsqrtf(ssa) * scl;
            rb = rsqrtf(ssb) * scl;
        }
        size_t r0 = rowbase + wm * 32 + ms * 16 + lr;
        #pragma unroll
        for (int ns = 0; ns < 4; ns++) {
            int c0 = coloff + wn * 32 + ns * 8 + lc * 2;
            float o0 = vv[ns][0] * ra, o1 = vv[ns][1] * ra;
            float o2 = vv[ns][2] * rb, o3 = vv[ns][3] * rb;
            if (mode != 0) { o0 = tf32r(o0); o1 = tf32r(o1); o2 = tf32r(o2); o3 = tf32r(o3); }
            *(float2*)(out + r0 * 192 + c0) = make_float2(o0, o1);
            *(float2*)(out + (r0 + 8) * 192 + c0) = make_float2(o2, o3);
        }
    }
}

// ---------------- attention: 4 windows per block (R10/R14 winner, unchanged) ----------------
#define WBUF 7168
#define ATT_SMEM ((2 * WBUF + 64 * 68) * 4)   // 74752 B

__global__ void __launch_bounds__(128) attn_kernel(const float* __restrict__ mask,
                                                   int nW, int WPG) {
    extern __shared__ float sm[];
    const uint32_t sm_u = smem_u32(sm);
    float* Ss = sm + 2 * WBUF;

    const int g = blockIdx.x;
    const int h = blockIdx.y;
    const int tid = threadIdx.x;
    const int lane = tid & 31;
    const int wid = tid >> 5;
    const int lr = lane >> 2;
    const int lc = lane & 3;
    const int m0 = wid * 16;
    const int r0 = m0 + lr, r1 = m0 + lr + 8;

    float bm[8][4];
    {
        const float* bmp = g_bias + h * 4096;
        const float* mkp = mask + (size_t)g * 4096;
        #pragma unroll
        for (int j = 0; j < 8; j++) {
            int c0 = j * 8 + lc * 2;
            float2 b0 = *(const float2*)(bmp + r0 * 64 + c0);
            float2 m0v = *(const float2*)(mkp + r0 * 64 + c0);
            float2 b1 = *(const float2*)(bmp + r1 * 64 + c0);
            float2 m1v = *(const float2*)(mkp + r1 * 64 + c0);
            bm[j][0] = b0.x + m0v.x;
            bm[j][1] = b0.y + m0v.y;
            bm[j][2] = b1.x + m1v.x;
            bm[j][3] = b1.y + m1v.y;
        }
    }

    auto issueW = [&](int st, int w) {
        size_t wbase = (size_t)(g + w * nW) * 64 * 192 + h * 32;
        uint32_t bu = sm_u + st * WBUF * 4;
        #pragma unroll
        for (int j = 0; j < 4; j++) {
            int id = j * 128 + tid;
            int r = id >> 3, c4 = (id & 7) << 2;
            size_t src = wbase + (size_t)r * 192 + c4;
            cp16(bu + (r * 36 + c4) * 4, g_q + src);
            cp16(bu + (2304 + r * 36 + c4) * 4, g_k + src);
            cp16(bu + (4608 + r * 40 + c4) * 4, g_v + src);
        }
    };

    issueW(0, 0); cp_commit();
    if (WPG > 1) { issueW(1, 1); cp_commit(); }

    #pragma unroll 1
    for (int w = 0; w < WPG; w++) {
        if (w + 1 < WPG) cp_wait<1>(); else cp_wait<0>();
        __syncthreads();
        const float* qs = sm + (w & 1) * WBUF;
        const float* ks = qs + 2304;
        const float* vs = qs + 4608;

        float acc[8][4];
        #pragma unroll
        for (int j = 0; j < 8; j++)
            #pragma unroll
            for (int c = 0; c < 4; c++) acc[j][c] = bm[j][c];
        #pragma unroll
        for (int kk = 0; kk < 32; kk += 8) {
            uint32_t af[4];
            af[0] = __float_as_uint(qs[r0 * 36 + kk + lc]);
            af[1] = __float_as_uint(qs[r1 * 36 + kk + lc]);
            af[2] = __float_as_uint(qs[r0 * 36 + kk + lc + 4]);
            af[3] = __float_as_uint(qs[r1 * 36 + kk + lc + 4]);
            #pragma unroll
            for (int j = 0; j < 8; j++) {
                uint32_t bf[2];
                bf[0] = __float_as_uint(ks[(j * 8 + lr) * 36 + kk + lc]);
                bf[1] = __float_as_uint(ks[(j * 8 + lr) * 36 + kk + lc + 4]);
                mma8(acc[j], af, bf);
            }
        }

        float mx0 = -1e30f, mx1 = -1e30f;
        #pragma unroll
        for (int j = 0; j < 8; j++) {
            mx0 = fmaxf(mx0, fmaxf(acc[j][0], acc[j][1]));
            mx1 = fmaxf(mx1, fmaxf(acc[j][2], acc[j][3]));
        }
        mx0 = fmaxf(mx0, __shfl_xor_sync(0xffffffffu, mx0, 1));
        mx0 = fmaxf(mx0, __shfl_xor_sync(0xffffffffu, mx0, 2));
        mx1 = fmaxf(mx1, __shfl_xor_sync(0xffffffffu, mx1, 1));
        mx1 = fmaxf(mx1, __shfl_xor_sync(0xffffffffu, mx1, 2));
        float s0 = 0.f, s1 = 0.f;
        #pragma unroll
        for (int j = 0; j < 8; j++) {
            float e0 = __expf(acc[j][0] - mx0); s0 += e0; acc[j][0] = tf32r(e0);
            float e1 = __expf(acc[j][1] - mx0); s0 += e1; acc[j][1] = tf32r(e1);
            float e2 = __expf(acc[j][2] - mx1); s1 += e2; acc[j][2] = tf32r(e2);
            float e3 = __expf(acc[j][3] - mx1); s1 += e3; acc[j][3] = tf32r(e3);
        }
        s0 += __shfl_xor_sync(0xffffffffu, s0, 1);
        s0 += __shfl_xor_sync(0xffffffffu, s0, 2);
        s1 += __shfl_xor_sync(0xffffffffu, s1, 1);
        s1 += __shfl_xor_sync(0xffffffffu, s1, 2);
        const float inv0 = 1.0f / s0;
        const float inv1 = 1.0f / s1;

        #pragma unroll
        for (int j = 0; j < 8; j++) {
            int c0 = j * 8 + lc * 2;
            *(float2*)&Ss[r0 * 68 + c0] = make_float2(acc[j][0], acc[j][1]);
            *(float2*)&Ss[r1 * 68 + c0] = make_float2(acc[j][2], acc[j][3]);
        }
        __syncwarp();

        float o[4][4];
        #pragma unroll
        for (int j = 0; j < 4; j++)
            #pragma unroll
            for (int c = 0; c < 4; c++) o[j][c] = 0.f;
        #pragma unroll
        for (int kk = 0; kk < 64; kk += 8) {
            uint32_t af[4];
            af[0] = __float_as_uint(Ss[r0 * 68 + kk + lc]);
            af[1] = __float_as_uint(Ss[r1 * 68 + kk + lc]);
            af[2] = __float_as_uint(Ss[r0 * 68 + kk + lc + 4]);
            af[3] = __float_as_uint(Ss[r1 * 68 + kk + lc + 4]);
            #pragma unroll
            for (int j = 0; j < 4; j++) {
                uint32_t bf[2];
                bf[0] = __float_as_uint(vs[(kk + lc) * 40 + j * 8 + lr]);
                bf[1] = __float_as_uint(vs[(kk + lc + 4) * 40 + j * 8 + lr]);
                mma8(o[j], af, bf);
            }
        }
        size_t obase = (size_t)(g + w * nW) * 64 * 192 + h * 32;
        #pragma unroll
        for (int j = 0; j < 4; j++) {
            int c0 = j * 8 + lc * 2;
            *(float2*)(g_t + obase + (size_t)r0 * 192 + c0) =
                make_float2(o[j][0] * inv0, o[j][1] * inv0);
            *(float2*)(g_t + obase + (size_t)r1 * 192 + c0) =
                make_float2(o[j][2] * inv1, o[j][3] * inv1);
        }

        __syncthreads();
        if (w + 2 < WPG) { issueW(w & 1, w + 2); cp_commit(); }
    }
}

// ---------------- launch ----------------
extern "C" void kernel_launch(void* const* d_in, const int* in_sizes, int n_in,
                              void* d_out, int out_size) {
    const float* hidden = (const float*)d_in[0];
    const float* mask   = (const float*)d_in[1];
    const float* ls     = (const float*)d_in[2];
    const float* fc1w   = (const float*)d_in[3];
    const float* fc1b   = (const float*)d_in[4];
    const float* fc2w   = (const float*)d_in[5];
    const float* qw     = (const float*)d_in[6];
    const float* qb     = (const float*)d_in[7];
    const float* kw     = (const float*)d_in[8];
    const float* vw     = (const float*)d_in[9];
    const float* vb     = (const float*)d_in[10];
    const float* pw     = (const float*)d_in[11];
    const float* pb     = (const float*)d_in[12];
    float* out = (float*)d_out;

    int B  = in_sizes[0] / (64 * 192);
    int nW = in_sizes[1] / (64 * 64);
    int WPG = B / nW;
    int mtiles = (B * 64) / 128;

    cudaFuncSetAttribute(gemm_kernel, cudaFuncAttributeMaxDynamicSharedMemorySize, GEMM_SMEM);
    cudaFuncSetAttribute(attn_kernel, cudaFuncAttributeMaxDynamicSharedMemorySize, ATT_SMEM);

    bias_mlp<<<29, 256>>>(ls, fc1w, fc1b, fc2w);
    bias_expand<<<48, 512>>>();
    gemm_kernel<<<dim3(mtiles, 9), 256, GEMM_SMEM>>>(hidden, qw, kw, vw, qb, vb, pw, pb, out, 0);
    attn_kernel<<<dim3(nW, HEADS), 128, ATT_SMEM>>>(mask, nW, WPG);
    gemm_kernel<<<dim3(mtiles, 3), 256, GEMM_SMEM>>>(hidden, qw, kw, vw, qb, vb, pw, pb, out, 1);
}

// round 16
// speedup vs baseline: 1.4491x; 1.0184x over previous
#include <cuda_runtime.h>
#include <cstdint>
#include <math.h>

#define HEADS 6
static constexpr size_t MAXELEM = (size_t)4096 * 64 * 192;

__device__ float g_q[MAXELEM];
__device__ float g_k[MAXELEM];
__device__ float g_v[MAXELEM];
__device__ float g_t[MAXELEM];
__device__ float g_bias[HEADS * 64 * 64];
__device__ float g_scale[HEADS];
__device__ float g_tab[225 * 6];

// ---------------- helpers ----------------
__device__ __forceinline__ uint32_t f2tf(float x) {
    uint32_t u;
    asm("cvt.rna.tf32.f32 %0, %1;" : "=r"(u) : "f"(x));
    return u;
}
__device__ __forceinline__ float tf32r(float x) { return __uint_as_float(f2tf(x)); }

__device__ __forceinline__ void mma8(float c[4], const uint32_t a[4], const uint32_t b[2]) {
    asm volatile(
        "mma.sync.aligned.m16n8k8.row.col.f32.tf32.tf32.f32 "
        "{%0,%1,%2,%3}, {%4,%5,%6,%7}, {%8,%9}, {%0,%1,%2,%3};"
        : "+f"(c[0]), "+f"(c[1]), "+f"(c[2]), "+f"(c[3])
        : "r"(a[0]), "r"(a[1]), "r"(a[2]), "r"(a[3]), "r"(b[0]), "r"(b[1]));
}

__device__ __forceinline__ uint32_t smem_u32(const void* p) {
    uint32_t a;
    asm("{ .reg .u64 t; cvta.to.shared.u64 t, %1; cvt.u32.u64 %0, t; }" : "=r"(a) : "l"(p));
    return a;
}
__device__ __forceinline__ void cp16(uint32_t dst, const void* src) {
    asm volatile("cp.async.cg.shared.global [%0], [%1], 16;" :: "r"(dst), "l"(src) : "memory");
}
__device__ __forceinline__ void cp_commit() {
    asm volatile("cp.async.commit_group;" ::: "memory");
}
template <int N>
__device__ __forceinline__ void cp_wait() {
    asm volatile("cp.async.wait_group %0;" :: "n"(N) : "memory");
}

// ---------------- bias / scale precompute (parallel) ----------------
__device__ __forceinline__ float slog(float d) {
    float x = d * (8.0f / 7.0f);
    float a = fabsf(x);
    float v = log2f(a + 1.0f) * (1.0f / 3.0f);
    return (x > 0.f) ? v : ((x < 0.f) ? -v : 0.f);
}

__global__ void bias_mlp(const float* __restrict__ ls,
                         const float* __restrict__ fc1w,
                         const float* __restrict__ fc1b,
                         const float* __restrict__ fc2w) {
    int lane = threadIdx.x & 31;
    int wid = threadIdx.x >> 5;
    if (blockIdx.x == 0 && threadIdx.x < HEADS)
        g_scale[threadIdx.x] = expf(fminf(ls[threadIdx.x], 4.6051702f));
    int e = blockIdx.x * 8 + wid;
    if (e >= 225) return;
    int i = e / 15, j = e % 15;
    float t0 = slog((float)(j - 7));
    float t1 = slog((float)(i - 7));
    float o[6] = {0.f, 0.f, 0.f, 0.f, 0.f, 0.f};
    for (int n = lane; n < 512; n += 32) {
        float hv = fmaxf(t0 * fc1w[n] + t1 * fc1w[512 + n] + fc1b[n], 0.f);
        const float* w2 = fc2w + n * 6;
        #pragma unroll
        for (int c = 0; c < 6; c++) o[c] += hv * w2[c];
    }
    #pragma unroll
    for (int c = 0; c < 6; c++) {
        #pragma unroll
        for (int s = 16; s > 0; s >>= 1) o[c] += __shfl_xor_sync(0xffffffffu, o[c], s);
    }
    if (lane == 0) {
        #pragma unroll
        for (int c = 0; c < 6; c++) g_tab[e * 6 + c] = o[c];
    }
}

__global__ void bias_expand() {
    int e = blockIdx.x * blockDim.x + threadIdx.x;
    int hh = e >> 12;
    int rem = e & 4095;
    int i = rem >> 6, j = rem & 63;
    int dy = (i >> 3) - (j >> 3);
    int dx = (i & 7) - (j & 7);
    float v = g_tab[((dy + 7) * 15 + (dx + 7)) * 6 + hh];
    g_bias[e] = 16.f / (1.f + expf(-v));
}

// ---------------- pipelined TF32 GEMM (R4 core): one 128x64 tile per block ----------------
// grid = (9, mtiles) for qkv / (3, mtiles) for proj: the variant blocks of one row-tile are
// launch-adjacent, so the A tile is fetched from DRAM once and served from L2 afterwards.
#define AS_STR 36   // 36 % 32 == 4 -> lr*36+lc covers 32 distinct banks
#define BS_STR 72   // lc*72+lr covers 32 distinct banks
#define A_ST (128 * AS_STR)          // floats per A stage
#define B_ST (32 * BS_STR)           // floats per B stage
#define GEMM_SMEM ((2 * A_ST + 2 * B_ST) * 4)   // 55296 B

// mode: 0 = +bias (proj/out), 1 = +bias,L2norm,*scale,tf32 (q),
//       2 = L2norm,tf32 (k), 3 = +bias,tf32 (v)
__global__ void __launch_bounds__(256) gemm_kernel(const float* __restrict__ Xin,
                                                   const float* __restrict__ qw,
                                                   const float* __restrict__ kw,
                                                   const float* __restrict__ vw,
                                                   const float* __restrict__ qb,
                                                   const float* __restrict__ vb,
                                                   const float* __restrict__ pw,
                                                   const float* __restrict__ pb,
                                                   float* __restrict__ dout,
                                                   int job) {
    extern __shared__ float sm[];
    float* As = sm;                 // [2][128][AS_STR]
    float* Bs = sm + 2 * A_ST;      // [2][32][BS_STR]
    const uint32_t as_u = smem_u32(sm);
    const uint32_t bs_u = as_u + 2 * A_ST * 4;

    const int tid = threadIdx.x;
    const int lane = tid & 31;
    const int wid = tid >> 5;
    const int wm = wid & 3;
    const int wn = wid >> 2;
    const int lr = lane >> 2;
    const int lc = lane & 3;
    const size_t rowbase = (size_t)blockIdx.y * 128;

    int coloff, mode;
    const float *A, *W, *bias;
    float* out;
    if (job) {
        A = g_t; W = pw; bias = pb; out = dout;
        coloff = blockIdx.x * 64; mode = 0;
    } else {
        A = Xin;
        int sel = blockIdx.x / 3;
        coloff = (blockIdx.x % 3) * 64;
        mode = sel + 1;
        W = (sel == 0) ? qw : (sel == 1) ? kw : vw;
        bias = (sel == 0) ? qb : (sel == 2) ? vb : (const float*)nullptr;
        out = (sel == 0) ? g_q : (sel == 1) ? g_k : g_v;
    }

    // async stage loaders
    auto issueA = [&](int st, int kt) {
        #pragma unroll
        for (int j = 0; j < 4; j++) {
            int id = j * 256 + tid;            // 0..1023
            int r = id >> 3;
            int ch = (id & 7) << 2;            // float col 0..28
            cp16(as_u + (st * A_ST + r * AS_STR + ch) * 4,
                 A + (rowbase + r) * 192 + kt * 32 + ch);
        }
    };
    auto issueB = [&](int st, int kt) {
        #pragma unroll
        for (int j = 0; j < 2; j++) {
            int id = j * 256 + tid;            // 0..511
            int r = id >> 4;
            int ch = (id & 15) << 2;           // float col 0..60
            cp16(bs_u + (st * B_ST + r * BS_STR + ch) * 4,
                 W + (size_t)(kt * 32 + r) * 192 + coloff + ch);
        }
    };

    float acc[2][4][4];
    #pragma unroll
    for (int a = 0; a < 2; a++)
        #pragma unroll
        for (int b = 0; b < 4; b++)
            #pragma unroll
            for (int c = 0; c < 4; c++) acc[a][b][c] = 0.f;

    issueA(0, 0); issueB(0, 0); cp_commit();
    issueA(1, 1); issueB(1, 1); cp_commit();

    #pragma unroll 1
    for (int kt = 0; kt < 6; kt++) {
        if (kt < 5) cp_wait<1>(); else cp_wait<0>();
        __syncthreads();
        const float* Ab = As + (kt & 1) * A_ST;
        const float* Bb = Bs + (kt & 1) * B_ST;
        #pragma unroll
        for (int kk = 0; kk < 32; kk += 8) {
            uint32_t af[2][4];
            #pragma unroll
            for (int ms = 0; ms < 2; ms++) {
                int r0 = wm * 32 + ms * 16 + lr;
                af[ms][0] = f2tf(Ab[r0 * AS_STR + kk + lc]);
                af[ms][1] = f2tf(Ab[(r0 + 8) * AS_STR + kk + lc]);
                af[ms][2] = f2tf(Ab[r0 * AS_STR + kk + lc + 4]);
                af[ms][3] = f2tf(Ab[(r0 + 8) * AS_STR + kk + lc + 4]);
            }
            #pragma unroll
            for (int ns = 0; ns < 4; ns++) {
                int c0 = wn * 32 + ns * 8 + lr;
                uint32_t bf[2];
                bf[0] = f2tf(Bb[(kk + lc) * BS_STR + c0]);
                bf[1] = f2tf(Bb[(kk + lc + 4) * BS_STR + c0]);
                mma8(acc[0][ns], af[0], bf);
                mma8(acc[1][ns], af[1], bf);
            }
        }
        __syncthreads();
        if (kt + 2 < 6) { issueA(kt & 1, kt + 2); issueB(kt & 1, kt + 2); cp_commit(); }
    }

    // epilogue
    float scl = (mode == 1) ? g_scale[(coloff >> 5) + wn] : 1.f;
    #pragma unroll
    for (int ms = 0; ms < 2; ms++) {
        float vv[4][4];
        float ssa = 0.f, ssb = 0.f;
        #pragma unroll
        for (int ns = 0; ns < 4; ns++) {
            int c0 = coloff + wn * 32 + ns * 8 + lc * 2;
            float b0 = bias ? bias[c0] : 0.f;
            float b1 = bias ? bias[c0 + 1] : 0.f;
            vv[ns][0] = acc[ms][ns][0] + b0;
            vv[ns][1] = acc[ms][ns][1] + b1;
            vv[ns][2] = acc[ms][ns][2] + b0;
            vv[ns][3] = acc[ms][ns][3] + b1;
            ssa += vv[ns][0] * vv[ns][0] + vv[ns][1] * vv[ns][1];
            ssb += vv[ns][2] * vv[ns][2] + vv[ns][3] * vv[ns][3];
        }
        float ra = 1.f, rb = 1.f;
        if (mode == 1 || mode == 2) {
            ssa += __shfl_xor_sync(0xffffffffu, ssa, 1);
            ssa += __shfl_xor_sync(0xffffffffu, ssa, 2);
            ssb += __shfl_xor_sync(0xffffffffu, ssb, 1);
            ssb += __shfl_xor_sync(0xffffffffu, ssb, 2);
            ra = rsqrtf(ssa) * scl;
            rb = rsqrtf(ssb) * scl;
        }
        size_t r0 = rowbase + wm * 32 + ms * 16 + lr;
        #pragma unroll
        for (int ns = 0; ns < 4; ns++) {
            int c0 = coloff + wn * 32 + ns * 8 + lc * 2;
            float o0 = vv[ns][0] * ra, o1 = vv[ns][1] * ra;
            float o2 = vv[ns][2] * rb, o3 = vv[ns][3] * rb;
            if (mode != 0) { o0 = tf32r(o0); o1 = tf32r(o1); o2 = tf32r(o2); o3 = tf32r(o3); }
            *(float2*)(out + r0 * 192 + c0) = make_float2(o0, o1);
            *(float2*)(out + (r0 + 8) * 192 + c0) = make_float2(o2, o3);
        }
    }
}

// ---------------- attention: 4 windows per block (R10/R14 winner, unchanged) ----------------
#define WBUF 7168
#define ATT_SMEM ((2 * WBUF + 64 * 68) * 4)   // 74752 B

__global__ void __launch_bounds__(128) attn_kernel(const float* __restrict__ mask,
                                                   int nW, int WPG) {
    extern __shared__ float sm[];
    const uint32_t sm_u = smem_u32(sm);
    float* Ss = sm + 2 * WBUF;

    const int g = blockIdx.x;
    const int h = blockIdx.y;
    const int tid = threadIdx.x;
    const int lane = tid & 31;
    const int wid = tid >> 5;
    const int lr = lane >> 2;
    const int lc = lane & 3;
    const int m0 = wid * 16;
    const int r0 = m0 + lr, r1 = m0 + lr + 8;

    float bm[8][4];
    {
        const float* bmp = g_bias + h * 4096;
        const float* mkp = mask + (size_t)g * 4096;
        #pragma unroll
        for (int j = 0; j < 8; j++) {
            int c0 = j * 8 + lc * 2;
            float2 b0 = *(const float2*)(bmp + r0 * 64 + c0);
            float2 m0v = *(const float2*)(mkp + r0 * 64 + c0);
            float2 b1 = *(const float2*)(bmp + r1 * 64 + c0);
            float2 m1v = *(const float2*)(mkp + r1 * 64 + c0);
            bm[j][0] = b0.x + m0v.x;
            bm[j][1] = b0.y + m0v.y;
            bm[j][2] = b1.x + m1v.x;
            bm[j][3] = b1.y + m1v.y;
        }
    }

    auto issueW = [&](int st, int w) {
        size_t wbase = (size_t)(g + w * nW) * 64 * 192 + h * 32;
        uint32_t bu = sm_u + st * WBUF * 4;
        #pragma unroll
        for (int j = 0; j < 4; j++) {
            int id = j * 128 + tid;
            int r = id >> 3, c4 = (id & 7) << 2;
            size_t src = wbase + (size_t)r * 192 + c4;
            cp16(bu + (r * 36 + c4) * 4, g_q + src);
            cp16(bu + (2304 + r * 36 + c4) * 4, g_k + src);
            cp16(bu + (4608 + r * 40 + c4) * 4, g_v + src);
        }
    };

    issueW(0, 0); cp_commit();
    if (WPG > 1) { issueW(1, 1); cp_commit(); }

    #pragma unroll 1
    for (int w = 0; w < WPG; w++) {
        if (w + 1 < WPG) cp_wait<1>(); else cp_wait<0>();
        __syncthreads();
        const float* qs = sm + (w & 1) * WBUF;
        const float* ks = qs + 2304;
        const float* vs = qs + 4608;

        float acc[8][4];
        #pragma unroll
        for (int j = 0; j < 8; j++)
            #pragma unroll
            for (int c = 0; c < 4; c++) acc[j][c] = bm[j][c];
        #pragma unroll
        for (int kk = 0; kk < 32; kk += 8) {
            uint32_t af[4];
            af[0] = __float_as_uint(qs[r0 * 36 + kk + lc]);
            af[1] = __float_as_uint(qs[r1 * 36 + kk + lc]);
            af[2] = __float_as_uint(qs[r0 * 36 + kk + lc + 4]);
            af[3] = __float_as_uint(qs[r1 * 36 + kk + lc + 4]);
            #pragma unroll
            for (int j = 0; j < 8; j++) {
                uint32_t bf[2];
                bf[0] = __float_as_uint(ks[(j * 8 + lr) * 36 + kk + lc]);
                bf[1] = __float_as_uint(ks[(j * 8 + lr) * 36 + kk + lc + 4]);
                mma8(acc[j], af, bf);
            }
        }

        float mx0 = -1e30f, mx1 = -1e30f;
        #pragma unroll
        for (int j = 0; j < 8; j++) {
            mx0 = fmaxf(mx0, fmaxf(acc[j][0], acc[j][1]));
            mx1 = fmaxf(mx1, fmaxf(acc[j][2], acc[j][3]));
        }
        mx0 = fmaxf(mx0, __shfl_xor_sync(0xffffffffu, mx0, 1));
        mx0 = fmaxf(mx0, __shfl_xor_sync(0xffffffffu, mx0, 2));
        mx1 = fmaxf(mx1, __shfl_xor_sync(0xffffffffu, mx1, 1));
        mx1 = fmaxf(mx1, __shfl_xor_sync(0xffffffffu, mx1, 2));
        float s0 = 0.f, s1 = 0.f;
        #pragma unroll
        for (int j = 0; j < 8; j++) {
            float e0 = __expf(acc[j][0] - mx0); s0 += e0; acc[j][0] = tf32r(e0);
            float e1 = __expf(acc[j][1] - mx0); s0 += e1; acc[j][1] = tf32r(e1);
            float e2 = __expf(acc[j][2] - mx1); s1 += e2; acc[j][2] = tf32r(e2);
            float e3 = __expf(acc[j][3] - mx1); s1 += e3; acc[j][3] = tf32r(e3);
        }
        s0 += __shfl_xor_sync(0xffffffffu, s0, 1);
        s0 += __shfl_xor_sync(0xffffffffu, s0, 2);
        s1 += __shfl_xor_sync(0xffffffffu, s1, 1);
        s1 += __shfl_xor_sync(0xffffffffu, s1, 2);
        const float inv0 = 1.0f / s0;
        const float inv1 = 1.0f / s1;

        #pragma unroll
        for (int j = 0; j < 8; j++) {
            int c0 = j * 8 + lc * 2;
            *(float2*)&Ss[r0 * 68 + c0] = make_float2(acc[j][0], acc[j][1]);
            *(float2*)&Ss[r1 * 68 + c0] = make_float2(acc[j][2], acc[j][3]);
        }
        __syncwarp();

        float o[4][4];
        #pragma unroll
        for (int j = 0; j < 4; j++)
            #pragma unroll
            for (int c = 0; c < 4; c++) o[j][c] = 0.f;
        #pragma unroll
        for (int kk = 0; kk < 64; kk += 8) {
            uint32_t af[4];
            af[0] = __float_as_uint(Ss[r0 * 68 + kk + lc]);
            af[1] = __float_as_uint(Ss[r1 * 68 + kk + lc]);
            af[2] = __float_as_uint(Ss[r0 * 68 + kk + lc + 4]);
            af[3] = __float_as_uint(Ss[r1 * 68 + kk + lc + 4]);
            #pragma unroll
            for (int j = 0; j < 4; j++) {
                uint32_t bf[2];
                bf[0] = __float_as_uint(vs[(kk + lc) * 40 + j * 8 + lr]);
                bf[1] = __float_as_uint(vs[(kk + lc + 4) * 40 + j * 8 + lr]);
                mma8(o[j], af, bf);
            }
        }
        size_t obase = (size_t)(g + w * nW) * 64 * 192 + h * 32;
        #pragma unroll
        for (int j = 0; j < 4; j++) {
            int c0 = j * 8 + lc * 2;
            *(float2*)(g_t + obase + (size_t)r0 * 192 + c0) =
                make_float2(o[j][0] * inv0, o[j][1] * inv0);
            *(float2*)(g_t + obase + (size_t)r1 * 192 + c0) =
                make_float2(o[j][2] * inv1, o[j][3] * inv1);
        }

        __syncthreads();
        if (w + 2 < WPG) { issueW(w & 1, w + 2); cp_commit(); }
    }
}

// ---------------- launch ----------------
extern "C" void kernel_launch(void* const* d_in, const int* in_sizes, int n_in,
                              void* d_out, int out_size) {
    const float* hidden = (const float*)d_in[0];
    const float* mask   = (const float*)d_in[1];
    const float* ls     = (const float*)d_in[2];
    const float* fc1w   = (const float*)d_in[3];
    const float* fc1b   = (const float*)d_in[4];
    const float* fc2w   = (const float*)d_in[5];
    const float* qw     = (const float*)d_in[6];
    const float* qb     = (const float*)d_in[7];
    const float* kw     = (const float*)d_in[8];
    const float* vw     = (const float*)d_in[9];
    const float* vb     = (const float*)d_in[10];
    const float* pw     = (const float*)d_in[11];
    const float* pb     = (const float*)d_in[12];
    float* out = (float*)d_out;

    int B  = in_sizes[0] / (64 * 192);
    int nW = in_sizes[1] / (64 * 64);
    int WPG = B / nW;
    int mtiles = (B * 64) / 128;

    cudaFuncSetAttribute(gemm_kernel, cudaFuncAttributeMaxDynamicSharedMemorySize, GEMM_SMEM);
    cudaFuncSetAttribute(attn_kernel, cudaFuncAttributeMaxDynamicSharedMemorySize, ATT_SMEM);

    bias_mlp<<<29, 256>>>(ls, fc1w, fc1b, fc2w);
    bias_expand<<<48, 512>>>();
    gemm_kernel<<<dim3(9, mtiles), 256, GEMM_SMEM>>>(hidden, qw, kw, vw, qb, vb, pw, pb, out, 0);
    attn_kernel<<<dim3(nW, HEADS), 128, ATT_SMEM>>>(mask, nW, WPG);
    gemm_kernel<<<dim3(3, mtiles), 256, GEMM_SMEM>>>(hidden, qw, kw, vw, qb, vb, pw, pb, out, 1);
}

// round 17
// speedup vs baseline: 1.4986x; 1.0341x over previous
#include <cuda_runtime.h>
#include <cstdint>
#include <math.h>

#define HEADS 6
static constexpr size_t MAXELEM = (size_t)4096 * 64 * 192;

__device__ float g_q[MAXELEM];
__device__ float g_k[MAXELEM];
__device__ float g_v[MAXELEM];
__device__ float g_t[MAXELEM];
__device__ float g_bias[HEADS * 64 * 64];
__device__ float g_scale[HEADS];
__device__ float g_tab[225 * 6];
__device__ float g_wq[192 * 192];
__device__ float g_wk[192 * 192];
__device__ float g_wv[192 * 192];
__device__ float g_wp[192 * 192];

// ---------------- helpers ----------------
__device__ __forceinline__ uint32_t f2tf(float x) {
    uint32_t u;
    asm("cvt.rna.tf32.f32 %0, %1;" : "=r"(u) : "f"(x));
    return u;
}
__device__ __forceinline__ float tf32r(float x) { return __uint_as_float(f2tf(x)); }

__device__ __forceinline__ void mma8(float c[4], const uint32_t a[4], const uint32_t b[2]) {
    asm volatile(
        "mma.sync.aligned.m16n8k8.row.col.f32.tf32.tf32.f32 "
        "{%0,%1,%2,%3}, {%4,%5,%6,%7}, {%8,%9}, {%0,%1,%2,%3};"
        : "+f"(c[0]), "+f"(c[1]), "+f"(c[2]), "+f"(c[3])
        : "r"(a[0]), "r"(a[1]), "r"(a[2]), "r"(a[3]), "r"(b[0]), "r"(b[1]));
}

__device__ __forceinline__ uint32_t smem_u32(const void* p) {
    uint32_t a;
    asm("{ .reg .u64 t; cvta.to.shared.u64 t, %1; cvt.u32.u64 %0, t; }" : "=r"(a) : "l"(p));
    return a;
}
__device__ __forceinline__ void cp16(uint32_t dst, const void* src) {
    asm volatile("cp.async.cg.shared.global [%0], [%1], 16;" :: "r"(dst), "l"(src) : "memory");
}
__device__ __forceinline__ void cp_commit() {
    asm volatile("cp.async.commit_group;" ::: "memory");
}
template <int N>
__device__ __forceinline__ void cp_wait() {
    asm volatile("cp.async.wait_group %0;" :: "n"(N) : "memory");
}

// ---------------- weight pre-round (removes B cvt from gemm inner loops) ----------------
__global__ void preround_w(const float* __restrict__ qw, const float* __restrict__ kw,
                           const float* __restrict__ vw, const float* __restrict__ pw) {
    int i = blockIdx.x * blockDim.x + threadIdx.x;
    if (i < 192 * 192) {
        g_wq[i] = tf32r(qw[i]);
        g_wk[i] = tf32r(kw[i]);
        g_wv[i] = tf32r(vw[i]);
        g_wp[i] = tf32r(pw[i]);
    }
}

// ---------------- bias / scale precompute (parallel) ----------------
__device__ __forceinline__ float slog(float d) {
    float x = d * (8.0f / 7.0f);
    float a = fabsf(x);
    float v = log2f(a + 1.0f) * (1.0f / 3.0f);
    return (x > 0.f) ? v : ((x < 0.f) ? -v : 0.f);
}

__global__ void bias_mlp(const float* __restrict__ ls,
                         const float* __restrict__ fc1w,
                         const float* __restrict__ fc1b,
                         const float* __restrict__ fc2w) {
    int lane = threadIdx.x & 31;
    int wid = threadIdx.x >> 5;
    if (blockIdx.x == 0 && threadIdx.x < HEADS)
        g_scale[threadIdx.x] = expf(fminf(ls[threadIdx.x], 4.6051702f));
    int e = blockIdx.x * 8 + wid;
    if (e >= 225) return;
    int i = e / 15, j = e % 15;
    float t0 = slog((float)(j - 7));
    float t1 = slog((float)(i - 7));
    float o[6] = {0.f, 0.f, 0.f, 0.f, 0.f, 0.f};
    for (int n = lane; n < 512; n += 32) {
        float hv = fmaxf(t0 * fc1w[n] + t1 * fc1w[512 + n] + fc1b[n], 0.f);
        const float* w2 = fc2w + n * 6;
        #pragma unroll
        for (int c = 0; c < 6; c++) o[c] += hv * w2[c];
    }
    #pragma unroll
    for (int c = 0; c < 6; c++) {
        #pragma unroll
        for (int s = 16; s > 0; s >>= 1) o[c] += __shfl_xor_sync(0xffffffffu, o[c], s);
    }
    if (lane == 0) {
        #pragma unroll
        for (int c = 0; c < 6; c++) g_tab[e * 6 + c] = o[c];
    }
}

__global__ void bias_expand() {
    int e = blockIdx.x * blockDim.x + threadIdx.x;
    int hh = e >> 12;
    int rem = e & 4095;
    int i = rem >> 6, j = rem & 63;
    int dy = (i >> 3) - (j >> 3);
    int dx = (i & 7) - (j & 7);
    float v = g_tab[((dy + 7) * 15 + (dx + 7)) * 6 + hh];
    g_bias[e] = 16.f / (1.f + expf(-v));
}

// ---------------- pipelined TF32 GEMM (R4 core): one 128x64 tile per block ----------------
// grid = (9, mtiles) qkv / (3, mtiles) proj. B pre-rounded; A cvt only when ACVT (qkv from X).
#define AS_STR 36
#define BS_STR 72
#define A_ST (128 * AS_STR)
#define B_ST (32 * BS_STR)
#define GEMM_SMEM ((2 * A_ST + 2 * B_ST) * 4)   // 55296 B

// mode: 0 = +bias (proj), 1 = +bias,L2norm,*scale,tf32 (q), 2 = L2norm,tf32 (k), 3 = +bias,tf32 (v)
template <bool ACVT>
__global__ void __launch_bounds__(256) gemm_kernel(const float* __restrict__ Xin,
                                                   const float* __restrict__ qb,
                                                   const float* __restrict__ vb,
                                                   const float* __restrict__ pb,
                                                   float* __restrict__ dout,
                                                   int job) {
    extern __shared__ float sm[];
    float* As = sm;                 // [2][128][AS_STR]
    float* Bs = sm + 2 * A_ST;      // [2][32][BS_STR]
    const uint32_t as_u = smem_u32(sm);
    const uint32_t bs_u = as_u + 2 * A_ST * 4;

    const int tid = threadIdx.x;
    const int lane = tid & 31;
    const int wid = tid >> 5;
    const int wm = wid & 3;
    const int wn = wid >> 2;
    const int lr = lane >> 2;
    const int lc = lane & 3;
    const size_t rowbase = (size_t)blockIdx.y * 128;

    int coloff, mode;
    const float *A, *W, *bias;
    float* out;
    if (job) {
        A = g_t; W = g_wp; bias = pb; out = dout;
        coloff = blockIdx.x * 64; mode = 0;
    } else {
        A = Xin;
        int sel = blockIdx.x / 3;
        coloff = (blockIdx.x % 3) * 64;
        mode = sel + 1;
        W = (sel == 0) ? g_wq : (sel == 1) ? g_wk : g_wv;
        bias = (sel == 0) ? qb : (sel == 2) ? vb : (const float*)nullptr;
        out = (sel == 0) ? g_q : (sel == 1) ? g_k : g_v;
    }

    auto issueA = [&](int st, int kt) {
        #pragma unroll
        for (int j = 0; j < 4; j++) {
            int id = j * 256 + tid;
            int r = id >> 3;
            int ch = (id & 7) << 2;
            cp16(as_u + (st * A_ST + r * AS_STR + ch) * 4,
                 A + (rowbase + r) * 192 + kt * 32 + ch);
        }
    };
    auto issueB = [&](int st, int kt) {
        #pragma unroll
        for (int j = 0; j < 2; j++) {
            int id = j * 256 + tid;
            int r = id >> 4;
            int ch = (id & 15) << 2;
            cp16(bs_u + (st * B_ST + r * BS_STR + ch) * 4,
                 W + (size_t)(kt * 32 + r) * 192 + coloff + ch);
        }
    };

    float acc[2][4][4];
    #pragma unroll
    for (int a = 0; a < 2; a++)
        #pragma unroll
        for (int b = 0; b < 4; b++)
            #pragma unroll
            for (int c = 0; c < 4; c++) acc[a][b][c] = 0.f;

    issueA(0, 0); issueB(0, 0); cp_commit();
    issueA(1, 1); issueB(1, 1); cp_commit();

    #pragma unroll 1
    for (int kt = 0; kt < 6; kt++) {
        if (kt < 5) cp_wait<1>(); else cp_wait<0>();
        __syncthreads();
        const float* Ab = As + (kt & 1) * A_ST;
        const float* Bb = Bs + (kt & 1) * B_ST;
        #pragma unroll
        for (int kk = 0; kk < 32; kk += 8) {
            uint32_t af[2][4];
            #pragma unroll
            for (int ms = 0; ms < 2; ms++) {
                int r0 = wm * 32 + ms * 16 + lr;
                if (ACVT) {
                    af[ms][0] = f2tf(Ab[r0 * AS_STR + kk + lc]);
                    af[ms][1] = f2tf(Ab[(r0 + 8) * AS_STR + kk + lc]);
                    af[ms][2] = f2tf(Ab[r0 * AS_STR + kk + lc + 4]);
                    af[ms][3] = f2tf(Ab[(r0 + 8) * AS_STR + kk + lc + 4]);
                } else {
                    af[ms][0] = __float_as_uint(Ab[r0 * AS_STR + kk + lc]);
                    af[ms][1] = __float_as_uint(Ab[(r0 + 8) * AS_STR + kk + lc]);
                    af[ms][2] = __float_as_uint(Ab[r0 * AS_STR + kk + lc + 4]);
                    af[ms][3] = __float_as_uint(Ab[(r0 + 8) * AS_STR + kk + lc + 4]);
                }
            }
            #pragma unroll
            for (int ns = 0; ns < 4; ns++) {
                int c0 = wn * 32 + ns * 8 + lr;
                uint32_t bf[2];
                bf[0] = __float_as_uint(Bb[(kk + lc) * BS_STR + c0]);
                bf[1] = __float_as_uint(Bb[(kk + lc + 4) * BS_STR + c0]);
                mma8(acc[0][ns], af[0], bf);
                mma8(acc[1][ns], af[1], bf);
            }
        }
        __syncthreads();
        if (kt + 2 < 6) { issueA(kt & 1, kt + 2); issueB(kt & 1, kt + 2); cp_commit(); }
    }

    // epilogue
    float scl = (mode == 1) ? g_scale[(coloff >> 5) + wn] : 1.f;
    #pragma unroll
    for (int ms = 0; ms < 2; ms++) {
        float vv[4][4];
        float ssa = 0.f, ssb = 0.f;
        #pragma unroll
        for (int ns = 0; ns < 4; ns++) {
            int c0 = coloff + wn * 32 + ns * 8 + lc * 2;
            float b0 = bias ? bias[c0] : 0.f;
            float b1 = bias ? bias[c0 + 1] : 0.f;
            vv[ns][0] = acc[ms][ns][0] + b0;
            vv[ns][1] = acc[ms][ns][1] + b1;
            vv[ns][2] = acc[ms][ns][2] + b0;
            vv[ns][3] = acc[ms][ns][3] + b1;
            ssa += vv[ns][0] * vv[ns][0] + vv[ns][1] * vv[ns][1];
            ssb += vv[ns][2] * vv[ns][2] + vv[ns][3] * vv[ns][3];
        }
        float ra = 1.f, rb = 1.f;
        if (mode == 1 || mode == 2) {
            ssa += __shfl_xor_sync(0xffffffffu, ssa, 1);
            ssa += __shfl_xor_sync(0xffffffffu, ssa, 2);
            ssb += __shfl_xor_sync(0xffffffffu, ssb, 1);
            ssb += __shfl_xor_sync(0xffffffffu, ssb, 2);
            ra = rsqrtf(ssa) * scl;
            rb = rsqrtf(ssb) * scl;
        }
        size_t r0 = rowbase + wm * 32 + ms * 16 + lr;
        #pragma unroll
        for (int ns = 0; ns < 4; ns++) {
            int c0 = coloff + wn * 32 + ns * 8 + lc * 2;
            float o0 = vv[ns][0] * ra, o1 = vv[ns][1] * ra;
            float o2 = vv[ns][2] * rb, o3 = vv[ns][3] * rb;
            if (mode != 0) { o0 = tf32r(o0); o1 = tf32r(o1); o2 = tf32r(o2); o3 = tf32r(o3); }
            *(float2*)(out + r0 * 192 + c0) = make_float2(o0, o1);
            *(float2*)(out + (r0 + 8) * 192 + c0) = make_float2(o2, o3);
        }
    }
}

// ---------------- attention: 4 windows per block (R10 winner; writes tf32-rounded g_t) ----------------
#define WBUF 7168
#define ATT_SMEM ((2 * WBUF + 64 * 68) * 4)   // 74752 B

__global__ void __launch_bounds__(128) attn_kernel(const float* __restrict__ mask,
                                                   int nW, int WPG) {
    extern __shared__ float sm[];
    const uint32_t sm_u = smem_u32(sm);
    float* Ss = sm + 2 * WBUF;

    const int g = blockIdx.x;
    const int h = blockIdx.y;
    const int tid = threadIdx.x;
    const int lane = tid & 31;
    const int wid = tid >> 5;
    const int lr = lane >> 2;
    const int lc = lane & 3;
    const int m0 = wid * 16;
    const int r0 = m0 + lr, r1 = m0 + lr + 8;

    float bm[8][4];
    {
        const float* bmp = g_bias + h * 4096;
        const float* mkp = mask + (size_t)g * 4096;
        #pragma unroll
        for (int j = 0; j < 8; j++) {
            int c0 = j * 8 + lc * 2;
            float2 b0 = *(const float2*)(bmp + r0 * 64 + c0);
            float2 m0v = *(const float2*)(mkp + r0 * 64 + c0);
            float2 b1 = *(const float2*)(bmp + r1 * 64 + c0);
            float2 m1v = *(const float2*)(mkp + r1 * 64 + c0);
            bm[j][0] = b0.x + m0v.x;
            bm[j][1] = b0.y + m0v.y;
            bm[j][2] = b1.x + m1v.x;
            bm[j][3] = b1.y + m1v.y;
        }
    }

    auto issueW = [&](int st, int w) {
        size_t wbase = (size_t)(g + w * nW) * 64 * 192 + h * 32;
        uint32_t bu = sm_u + st * WBUF * 4;
        #pragma unroll
        for (int j = 0; j < 4; j++) {
            int id = j * 128 + tid;
            int r = id >> 3, c4 = (id & 7) << 2;
            size_t src = wbase + (size_t)r * 192 + c4;
            cp16(bu + (r * 36 + c4) * 4, g_q + src);
            cp16(bu + (2304 + r * 36 + c4) * 4, g_k + src);
            cp16(bu + (4608 + r * 40 + c4) * 4, g_v + src);
        }
    };

    issueW(0, 0); cp_commit();
    if (WPG > 1) { issueW(1, 1); cp_commit(); }

    #pragma unroll 1
    for (int w = 0; w < WPG; w++) {
        if (w + 1 < WPG) cp_wait<1>(); else cp_wait<0>();
        __syncthreads();
        const float* qs = sm + (w & 1) * WBUF;
        const float* ks = qs + 2304;
        const float* vs = qs + 4608;

        float acc[8][4];
        #pragma unroll
        for (int j = 0; j < 8; j++)
            #pragma unroll
            for (int c = 0; c < 4; c++) acc[j][c] = bm[j][c];
        #pragma unroll
        for (int kk = 0; kk < 32; kk += 8) {
            uint32_t af[4];
            af[0] = __float_as_uint(qs[r0 * 36 + kk + lc]);
            af[1] = __float_as_uint(qs[r1 * 36 + kk + lc]);
            af[2] = __float_as_uint(qs[r0 * 36 + kk + lc + 4]);
            af[3] = __float_as_uint(qs[r1 * 36 + kk + lc + 4]);
            #pragma unroll
            for (int j = 0; j < 8; j++) {
                uint32_t bf[2];
                bf[0] = __float_as_uint(ks[(j * 8 + lr) * 36 + kk + lc]);
                bf[1] = __float_as_uint(ks[(j * 8 + lr) * 36 + kk + lc + 4]);
                mma8(acc[j], af, bf);
            }
        }

        float mx0 = -1e30f, mx1 = -1e30f;
        #pragma unroll
        for (int j = 0; j < 8; j++) {
            mx0 = fmaxf(mx0, fmaxf(acc[j][0], acc[j][1]));
            mx1 = fmaxf(mx1, fmaxf(acc[j][2], acc[j][3]));
        }
        mx0 = fmaxf(mx0, __shfl_xor_sync(0xffffffffu, mx0, 1));
        mx0 = fmaxf(mx0, __shfl_xor_sync(0xffffffffu, mx0, 2));
        mx1 = fmaxf(mx1, __shfl_xor_sync(0xffffffffu, mx1, 1));
        mx1 = fmaxf(mx1, __shfl_xor_sync(0xffffffffu, mx1, 2));
        float s0 = 0.f, s1 = 0.f;
        #pragma unroll
        for (int j = 0; j < 8; j++) {
            float e0 = __expf(acc[j][0] - mx0); s0 += e0; acc[j][0] = tf32r(e0);
            float e1 = __expf(acc[j][1] - mx0); s0 += e1; acc[j][1] = tf32r(e1);
            float e2 = __expf(acc[j][2] - mx1); s1 += e2; acc[j][2] = tf32r(e2);
            float e3 = __expf(acc[j][3] - mx1); s1 += e3; acc[j][3] = tf32r(e3);
        }
        s0 += __shfl_xor_sync(0xffffffffu, s0, 1);
        s0 += __shfl_xor_sync(0xffffffffu, s0, 2);
        s1 += __shfl_xor_sync(0xffffffffu, s1, 1);
        s1 += __shfl_xor_sync(0xffffffffu, s1, 2);
        const float inv0 = 1.0f / s0;
        const float inv1 = 1.0f / s1;

        #pragma unroll
        for (int j = 0; j < 8; j++) {
            int c0 = j * 8 + lc * 2;
            *(float2*)&Ss[r0 * 68 + c0] = make_float2(acc[j][0], acc[j][1]);
            *(float2*)&Ss[r1 * 68 + c0] = make_float2(acc[j][2], acc[j][3]);
        }
        __syncwarp();

        float o[4][4];
        #pragma unroll
        for (int j = 0; j < 4; j++)
            #pragma unroll
            for (int c = 0; c < 4; c++) o[j][c] = 0.f;
        #pragma unroll
        for (int kk = 0; kk < 64; kk += 8) {
            uint32_t af[4];
            af[0] = __float_as_uint(Ss[r0 * 68 + kk + lc]);
            af[1] = __float_as_uint(Ss[r1 * 68 + kk + lc]);
            af[2] = __float_as_uint(Ss[r0 * 68 + kk + lc + 4]);
            af[3] = __float_as_uint(Ss[r1 * 68 + kk + lc + 4]);
            #pragma unroll
            for (int j = 0; j < 4; j++) {
                uint32_t bf[2];
                bf[0] = __float_as_uint(vs[(kk + lc) * 40 + j * 8 + lr]);
                bf[1] = __float_as_uint(vs[(kk + lc + 4) * 40 + j * 8 + lr]);
                mma8(o[j], af, bf);
            }
        }
        size_t obase = (size_t)(g + w * nW) * 64 * 192 + h * 32;
        #pragma unroll
        for (int j = 0; j < 4; j++) {
            int c0 = j * 8 + lc * 2;
            *(float2*)(g_t + obase + (size_t)r0 * 192 + c0) =
                make_float2(tf32r(o[j][0] * inv0), tf32r(o[j][1] * inv0));
            *(float2*)(g_t + obase + (size_t)r1 * 192 + c0) =
                make_float2(tf32r(o[j][2] * inv1), tf32r(o[j][3] * inv1));
        }

        __syncthreads();
        if (w + 2 < WPG) { issueW(w & 1, w + 2); cp_commit(); }
    }
}

// ---------------- launch ----------------
extern "C" void kernel_launch(void* const* d_in, const int* in_sizes, int n_in,
                              void* d_out, int out_size) {
    const float* hidden = (const float*)d_in[0];
    const float* mask   = (const float*)d_in[1];
    const float* ls     = (const float*)d_in[2];
    const float* fc1w   = (const float*)d_in[3];
    const float* fc1b   = (const float*)d_in[4];
    const float* fc2w   = (const float*)d_in[5];
    const float* qw     = (const float*)d_in[6];
    const float* qb     = (const float*)d_in[7];
    const float* kw     = (const float*)d_in[8];
    const float* vw     = (const float*)d_in[9];
    const float* vb     = (const float*)d_in[10];
    const float* pw     = (const float*)d_in[11];
    const float* pb     = (const float*)d_in[12];
    float* out = (float*)d_out;

    int B  = in_sizes[0] / (64 * 192);
    int nW = in_sizes[1] / (64 * 64);
    int WPG = B / nW;
    int mtiles = (B * 64) / 128;

    cudaFuncSetAttribute(gemm_kernel<true>, cudaFuncAttributeMaxDynamicSharedMemorySize, GEMM_SMEM);
    cudaFuncSetAttribute(gemm_kernel<false>, cudaFuncAttributeMaxDynamicSharedMemorySize, GEMM_SMEM);
    cudaFuncSetAttribute(attn_kernel, cudaFuncAttributeMaxDynamicSharedMemorySize, ATT_SMEM);

    preround_w<<<144, 256>>>(qw, kw, vw, pw);
    bias_mlp<<<29, 256>>>(ls, fc1w, fc1b, fc2w);
    bias_expand<<<48, 512>>>();
    gemm_kernel<true><<<dim3(9, mtiles), 256, GEMM_SMEM>>>(hidden, qb, vb, pb, out, 0);
    attn_kernel<<<dim3(nW, HEADS), 128, ATT_SMEM>>>(mask, nW, WPG);
    gemm_kernel<false><<<dim3(3, mtiles), 256, GEMM_SMEM>>>(hidden, qb, vb, pb, out, 1);
}